// round 1
// baseline (speedup 1.0000x reference)
#include <cuda_runtime.h>
#include <math.h>

#define N_NODES 50000
#define N_EDGES 1600000
#define T_STEPS 4
#define C 128           // IN_CH == HID == 128
#define OUT_DIM 16
#define TILE_M 32

// ---------------- scratch (device globals; no allocs allowed) ----------------
__device__ int   g_count[N_NODES];
__device__ int   g_off[N_NODES + 1];
__device__ int   g_cur[N_NODES];
__device__ int   g_csr[N_EDGES];
__device__ __align__(16) float g_aggx[N_NODES * C];   // deg-normalized aggregated x
__device__ __align__(16) float g_zsum[C];
__device__ __align__(16) float g_h[C];

// ---------------- init: zero h and counts (once per launch) ----------------
__global__ void init_kernel() {
    int i = blockIdx.x * blockDim.x + threadIdx.x;
    if (i < C) g_h[i] = 0.f;
    if (i < N_NODES) g_count[i] = 0;
}

// ---------------- CSR build ----------------
__global__ void count_kernel(const int* __restrict__ dst) {
    int e = blockIdx.x * blockDim.x + threadIdx.x;
    if (e < N_EDGES) atomicAdd(&g_count[dst[e]], 1);
}

// single-block exclusive scan of counts -> offsets & cursors; also resets
// counts (for next timestep) and zeros zsum for this timestep's GEMM.
__global__ void scan_kernel() {
    const int tid = threadIdx.x;                 // 1024 threads
    const int CH = (N_NODES + 1023) / 1024;      // 49
    int s = tid * CH;
    int e = min(s + CH, N_NODES);

    int sum = 0;
    for (int i = s; i < e; i++) sum += g_count[i];

    __shared__ int wsum[32];
    int lane = tid & 31, wid = tid >> 5;
    int v = sum;
    #pragma unroll
    for (int o = 1; o < 32; o <<= 1) {
        int t = __shfl_up_sync(0xffffffff, v, o);
        if (lane >= o) v += t;
    }
    if (lane == 31) wsum[wid] = v;
    __syncthreads();
    if (wid == 0) {
        int w = wsum[lane];
        #pragma unroll
        for (int o = 1; o < 32; o <<= 1) {
            int t = __shfl_up_sync(0xffffffff, w, o);
            if (lane >= o) w += t;
        }
        wsum[lane] = w;
    }
    __syncthreads();
    int ex = v - sum + (wid > 0 ? wsum[wid - 1] : 0);

    int run = ex;
    for (int i = s; i < e; i++) {
        int c = g_count[i];
        g_off[i] = run;
        g_cur[i] = run;
        run += c;
        g_count[i] = 0;     // reset for next timestep
    }
    if (tid == 1023) g_off[N_NODES] = run;
    if (tid < C) g_zsum[tid] = 0.f;
}

__global__ void place_kernel(const int* __restrict__ src, const int* __restrict__ dst) {
    int e = blockIdx.x * blockDim.x + threadIdx.x;
    if (e < N_EDGES) {
        int p = atomicAdd(&g_cur[dst[e]], 1);
        g_csr[p] = src[e];
    }
}

// ---------------- gather: warp per node, accumulate neighbors + self ----------------
__global__ __launch_bounds__(256) void gather_kernel(const float* __restrict__ x) {
    int warp = (blockIdx.x * blockDim.x + threadIdx.x) >> 5;
    int lane = threadIdx.x & 31;
    if (warp >= N_NODES) return;

    const float4* __restrict__ x4 = (const float4*)x;
    float4 acc = x4[warp * 32 + lane];   // self loop
    int beg = g_off[warp], end = g_off[warp + 1];

    int i = beg;
    for (; i + 1 < end; i += 2) {
        int s0 = g_csr[i];
        int s1 = g_csr[i + 1];
        float4 a = x4[s0 * 32 + lane];
        float4 b = x4[s1 * 32 + lane];
        acc.x += a.x + b.x; acc.y += a.y + b.y;
        acc.z += a.z + b.z; acc.w += a.w + b.w;
    }
    if (i < end) {
        int s0 = g_csr[i];
        float4 a = x4[s0 * 32 + lane];
        acc.x += a.x; acc.y += a.y; acc.z += a.z; acc.w += a.w;
    }

    float inv = 1.f / (float)(end - beg + 1);   // deg includes self loop, >=1
    float4 o;
    o.x = acc.x * inv; o.y = acc.y * inv; o.z = acc.z * inv; o.w = acc.w * inv;
    ((float4*)g_aggx)[warp * 32 + lane] = o;
}

// ---------------- fused GEMM + relu + column-mean partial ----------------
// u = (aggx) @ W^T + b ; zsum += sum_n relu(u_n). Never materializes u.
#define GEMM_SMEM_FLOATS (C*C + C + TILE_M*C + 8*C)
__global__ __launch_bounds__(256) void gemm_mean_kernel(const float* __restrict__ W,
                                                        const float* __restrict__ b) {
    extern __shared__ float smem[];
    float* sWt = smem;                     // [k][j] transposed W, 16384
    float* sB  = smem + C * C;             // 128
    float* sA  = sB + C;                   // 32x128 = 4096
    float* red = sA + TILE_M * C;          // 8x128 = 1024

    int tid = threadIdx.x;
    for (int i = tid; i < C * C; i += 256) {
        int j = i >> 7, k = i & 127;
        sWt[k * C + j] = W[i];
    }
    if (tid < C) sB[tid] = b[tid];

    int lane = tid & 31, warp = tid >> 5;   // 8 warps; warp handles 4 nodes
    float4 csum = make_float4(0.f, 0.f, 0.f, 0.f);

    const int nTiles = (N_NODES + TILE_M - 1) / TILE_M;
    const float4* w4p = ((const float4*)sWt) + lane;   // cols 4*lane..4*lane+3

    for (int tile = blockIdx.x; tile < nTiles; tile += gridDim.x) {
        __syncthreads();   // sWt ready (1st iter) / sA free (later iters)
        int n0 = tile * TILE_M;
        const float4* A4 = ((const float4*)g_aggx) + n0 * 32;
        float4* sA4 = (float4*)sA;
        #pragma unroll
        for (int i = 0; i < 4; i++) {
            int idx = tid + i * 256;             // 1024 float4s
            int node = n0 + (idx >> 5);
            float4 v = make_float4(0.f, 0.f, 0.f, 0.f);
            if (node < N_NODES) v = A4[idx];
            sA4[idx] = v;
        }
        __syncthreads();

        const float* a0 = &sA[(warp * 4 + 0) * C];
        const float* a1 = &sA[(warp * 4 + 1) * C];
        const float* a2 = &sA[(warp * 4 + 2) * C];
        const float* a3 = &sA[(warp * 4 + 3) * C];

        float4 acc0 = make_float4(0,0,0,0), acc1 = acc0, acc2 = acc0, acc3 = acc0;
        #pragma unroll 4
        for (int k = 0; k < C; k++) {
            float4 w = w4p[k * 32];
            float x0 = a0[k], x1 = a1[k], x2 = a2[k], x3 = a3[k];
            acc0.x = fmaf(x0, w.x, acc0.x); acc0.y = fmaf(x0, w.y, acc0.y);
            acc0.z = fmaf(x0, w.z, acc0.z); acc0.w = fmaf(x0, w.w, acc0.w);
            acc1.x = fmaf(x1, w.x, acc1.x); acc1.y = fmaf(x1, w.y, acc1.y);
            acc1.z = fmaf(x1, w.z, acc1.z); acc1.w = fmaf(x1, w.w, acc1.w);
            acc2.x = fmaf(x2, w.x, acc2.x); acc2.y = fmaf(x2, w.y, acc2.y);
            acc2.z = fmaf(x2, w.z, acc2.z); acc2.w = fmaf(x2, w.w, acc2.w);
            acc3.x = fmaf(x3, w.x, acc3.x); acc3.y = fmaf(x3, w.y, acc3.y);
            acc3.z = fmaf(x3, w.z, acc3.z); acc3.w = fmaf(x3, w.w, acc3.w);
        }

        float4 bb = ((const float4*)sB)[lane];
        int nb = n0 + warp * 4;
        if (nb + 0 < N_NODES) {
            csum.x += fmaxf(acc0.x + bb.x, 0.f); csum.y += fmaxf(acc0.y + bb.y, 0.f);
            csum.z += fmaxf(acc0.z + bb.z, 0.f); csum.w += fmaxf(acc0.w + bb.w, 0.f);
        }
        if (nb + 1 < N_NODES) {
            csum.x += fmaxf(acc1.x + bb.x, 0.f); csum.y += fmaxf(acc1.y + bb.y, 0.f);
            csum.z += fmaxf(acc1.z + bb.z, 0.f); csum.w += fmaxf(acc1.w + bb.w, 0.f);
        }
        if (nb + 2 < N_NODES) {
            csum.x += fmaxf(acc2.x + bb.x, 0.f); csum.y += fmaxf(acc2.y + bb.y, 0.f);
            csum.z += fmaxf(acc2.z + bb.z, 0.f); csum.w += fmaxf(acc2.w + bb.w, 0.f);
        }
        if (nb + 3 < N_NODES) {
            csum.x += fmaxf(acc3.x + bb.x, 0.f); csum.y += fmaxf(acc3.y + bb.y, 0.f);
            csum.z += fmaxf(acc3.z + bb.z, 0.f); csum.w += fmaxf(acc3.w + bb.w, 0.f);
        }
    }

    // block reduce per column, then one global atomic per column
    ((float4*)(red + warp * C))[lane] = csum;
    __syncthreads();
    if (tid < C) {
        float s = 0.f;
        #pragma unroll
        for (int w = 0; w < 8; w++) s += red[w * C + tid];
        atomicAdd(&g_zsum[tid], s);
    }
}

// ---------------- GRU cell (single block, 128 threads) ----------------
__global__ void gru_kernel(const float* __restrict__ Wih, const float* __restrict__ Whh,
                           const float* __restrict__ bih, const float* __restrict__ bhh) {
    __shared__ __align__(16) float z[C];
    __shared__ __align__(16) float hs[C];
    int tid = threadIdx.x;
    z[tid]  = g_zsum[tid] * (1.f / (float)N_NODES);
    hs[tid] = g_h[tid];
    __syncthreads();

    float gir = bih[tid], giz = bih[C + tid], gin = bih[2 * C + tid];
    float ghr = bhh[tid], ghz = bhh[C + tid], ghn = bhh[2 * C + tid];

    const float4* Wih4 = (const float4*)Wih;
    const float4* Whh4 = (const float4*)Whh;
    const float4* z4 = (const float4*)z;
    const float4* h4 = (const float4*)hs;

    #pragma unroll 8
    for (int k = 0; k < 32; k++) {
        float4 zv = z4[k], hv = h4[k];
        float4 w;
        w = Wih4[(0 * C + tid) * 32 + k]; gir += zv.x*w.x + zv.y*w.y + zv.z*w.z + zv.w*w.w;
        w = Wih4[(1 * C + tid) * 32 + k]; giz += zv.x*w.x + zv.y*w.y + zv.z*w.z + zv.w*w.w;
        w = Wih4[(2 * C + tid) * 32 + k]; gin += zv.x*w.x + zv.y*w.y + zv.z*w.z + zv.w*w.w;
        w = Whh4[(0 * C + tid) * 32 + k]; ghr += hv.x*w.x + hv.y*w.y + hv.z*w.z + hv.w*w.w;
        w = Whh4[(1 * C + tid) * 32 + k]; ghz += hv.x*w.x + hv.y*w.y + hv.z*w.z + hv.w*w.w;
        w = Whh4[(2 * C + tid) * 32 + k]; ghn += hv.x*w.x + hv.y*w.y + hv.z*w.z + hv.w*w.w;
    }

    float r  = 1.f / (1.f + expf(-(gir + ghr)));
    float zg = 1.f / (1.f + expf(-(giz + ghz)));
    float ng = tanhf(gin + r * ghn);
    g_h[tid] = (1.f - zg) * ng + zg * hs[tid];
}

// ---------------- classifier ----------------
__global__ void cls_kernel(const float* __restrict__ Wc, const float* __restrict__ bc,
                           float* __restrict__ out) {
    int tid = threadIdx.x;
    if (tid < OUT_DIM) {
        float acc = bc[tid];
        const float4* W4 = (const float4*)Wc;
        const float4* h4 = (const float4*)g_h;
        #pragma unroll
        for (int k = 0; k < 32; k++) {
            float4 w = W4[tid * 32 + k], h = h4[k];
            acc += w.x * h.x + w.y * h.y + w.z * h.z + w.w * h.w;
        }
        out[tid] = acc;
    }
}

// ---------------- launch ----------------
extern "C" void kernel_launch(void* const* d_in, const int* in_sizes, int n_in,
                              void* d_out, int out_size) {
    const float* xs   = (const float*)d_in[0];
    const int*   edges= (const int*)  d_in[1];
    const float* Wg   = (const float*)d_in[2];
    const float* bg   = (const float*)d_in[3];
    const float* Wih  = (const float*)d_in[4];
    const float* Whh  = (const float*)d_in[5];
    const float* bih  = (const float*)d_in[6];
    const float* bhh  = (const float*)d_in[7];
    const float* Wc   = (const float*)d_in[8];
    const float* bc   = (const float*)d_in[9];
    float* out = (float*)d_out;

    const int smem_bytes = GEMM_SMEM_FLOATS * sizeof(float);   // ~86.5 KB
    cudaFuncSetAttribute(gemm_mean_kernel,
                         cudaFuncAttributeMaxDynamicSharedMemorySize, smem_bytes);

    init_kernel<<<(N_NODES + 255) / 256, 256>>>();

    for (int t = 0; t < T_STEPS; t++) {
        const int* src = edges + (size_t)t * 2 * N_EDGES;
        const int* dst = src + N_EDGES;
        const float* x = xs + (size_t)t * N_NODES * C;

        count_kernel<<<(N_EDGES + 255) / 256, 256>>>(dst);
        scan_kernel<<<1, 1024>>>();
        place_kernel<<<(N_EDGES + 255) / 256, 256>>>(src, dst);
        gather_kernel<<<(N_NODES * 32 + 255) / 256, 256>>>(x);
        gemm_mean_kernel<<<296, 256, smem_bytes>>>(Wg, bg);
        gru_kernel<<<1, C>>>(Wih, Whh, bih, bhh);
    }
    cls_kernel<<<1, 32>>>(Wc, bc, out);
}

// round 2
// speedup vs baseline: 1.9758x; 1.9758x over previous
#include <cuda_runtime.h>
#include <cuda_bf16.h>
#include <math.h>

#define N_NODES 50000
#define N_EDGES 1600000
#define T_STEPS 4
#define C 128
#define OUT_DIM 16

// ---------------- scratch (device globals; no allocs allowed) ----------------
__device__ int   g_cnt[T_STEPS][N_NODES];
__device__ int   g_off[T_STEPS][N_NODES + 1];
__device__ int   g_cur[T_STEPS][N_NODES];
__device__ int   g_csr[T_STEPS][N_EDGES];
__device__ __align__(16) __nv_bfloat16 g_aggx_bf[N_NODES * C];
__device__ __align__(16) __nv_bfloat16 g_Wbf[C * C];
__device__ __align__(16) float g_zsum[T_STEPS][C];
__device__ __align__(16) float g_h[C];

// ---------------- init: zero counts/h/zsum, convert W to bf16 ----------------
__global__ void init_kernel(const float* __restrict__ W) {
    int i = blockIdx.x * blockDim.x + threadIdx.x;
    if (i < T_STEPS * N_NODES) ((int*)g_cnt)[i] = 0;
    if (i < C * C) g_Wbf[i] = __float2bfloat16(W[i]);
    if (i < T_STEPS * C) ((float*)g_zsum)[i] = 0.f;
    if (i < C) g_h[i] = 0.f;
}

// ---------------- CSR build: all 4 timesteps at once ----------------
__global__ void count_all_kernel(const int* __restrict__ edges) {
    int t = blockIdx.y;
    int e4 = blockIdx.x * blockDim.x + threadIdx.x;      // edge/4 index
    const int4* dst4 = (const int4*)(edges + (size_t)t * 2 * N_EDGES + N_EDGES);
    if (e4 < N_EDGES / 4) {
        int4 d = dst4[e4];
        atomicAdd(&g_cnt[t][d.x], 1);
        atomicAdd(&g_cnt[t][d.y], 1);
        atomicAdd(&g_cnt[t][d.z], 1);
        atomicAdd(&g_cnt[t][d.w], 1);
    }
}

__global__ void scan_all_kernel() {
    int t = blockIdx.y;
    const int tid = threadIdx.x;                 // 1024 threads
    const int CH = (N_NODES + 1023) / 1024;      // 49
    int s = tid * CH;
    int e = min(s + CH, N_NODES);

    int sum = 0;
    for (int i = s; i < e; i++) sum += g_cnt[t][i];

    __shared__ int wsum[32];
    int lane = tid & 31, wid = tid >> 5;
    int v = sum;
    #pragma unroll
    for (int o = 1; o < 32; o <<= 1) {
        int x = __shfl_up_sync(0xffffffff, v, o);
        if (lane >= o) v += x;
    }
    if (lane == 31) wsum[wid] = v;
    __syncthreads();
    if (wid == 0) {
        int w = wsum[lane];
        #pragma unroll
        for (int o = 1; o < 32; o <<= 1) {
            int x = __shfl_up_sync(0xffffffff, w, o);
            if (lane >= o) w += x;
        }
        wsum[lane] = w;
    }
    __syncthreads();
    int ex = v - sum + (wid > 0 ? wsum[wid - 1] : 0);

    int run = ex;
    for (int i = s; i < e; i++) {
        int c = g_cnt[t][i];
        g_off[t][i] = run;
        g_cur[t][i] = run;
        run += c;
    }
    if (tid == 1023) g_off[t][N_NODES] = run;
}

__global__ void place_all_kernel(const int* __restrict__ edges) {
    int t = blockIdx.y;
    int e4 = blockIdx.x * blockDim.x + threadIdx.x;
    const int* base = edges + (size_t)t * 2 * N_EDGES;
    const int4* src4 = (const int4*)base;
    const int4* dst4 = (const int4*)(base + N_EDGES);
    if (e4 < N_EDGES / 4) {
        int4 s = src4[e4];
        int4 d = dst4[e4];
        int p;
        p = atomicAdd(&g_cur[t][d.x], 1); g_csr[t][p] = s.x;
        p = atomicAdd(&g_cur[t][d.y], 1); g_csr[t][p] = s.y;
        p = atomicAdd(&g_cur[t][d.z], 1); g_csr[t][p] = s.z;
        p = atomicAdd(&g_cur[t][d.w], 1); g_csr[t][p] = s.w;
    }
}

// ---------------- gather: warp per node, fp32 accum, bf16 output ----------------
__global__ __launch_bounds__(256) void gather_kernel(const float* __restrict__ x, int t) {
    int warp = (blockIdx.x * blockDim.x + threadIdx.x) >> 5;
    int lane = threadIdx.x & 31;
    if (warp >= N_NODES) return;

    const float4* __restrict__ x4 = (const float4*)x;
    const int* __restrict__ csr = g_csr[t];
    float4 acc = x4[warp * 32 + lane];   // self loop
    int beg = g_off[t][warp], end = g_off[t][warp + 1];

    int i = beg;
    for (; i + 3 < end; i += 4) {
        int s0 = csr[i], s1 = csr[i + 1], s2 = csr[i + 2], s3 = csr[i + 3];
        float4 a = x4[s0 * 32 + lane];
        float4 b = x4[s1 * 32 + lane];
        float4 c = x4[s2 * 32 + lane];
        float4 d = x4[s3 * 32 + lane];
        acc.x += (a.x + b.x) + (c.x + d.x);
        acc.y += (a.y + b.y) + (c.y + d.y);
        acc.z += (a.z + b.z) + (c.z + d.z);
        acc.w += (a.w + b.w) + (c.w + d.w);
    }
    for (; i < end; i++) {
        int s0 = csr[i];
        float4 a = x4[s0 * 32 + lane];
        acc.x += a.x; acc.y += a.y; acc.z += a.z; acc.w += a.w;
    }

    float inv = 1.f / (float)(end - beg + 1);
    __nv_bfloat162 p0 = __floats2bfloat162_rn(acc.x * inv, acc.y * inv);
    __nv_bfloat162 p1 = __floats2bfloat162_rn(acc.z * inv, acc.w * inv);
    uint2 o;
    o.x = *(unsigned int*)&p0;
    o.y = *(unsigned int*)&p1;
    ((uint2*)g_aggx_bf)[warp * 32 + lane] = o;
}

// ---------------- bf16 tensor-core GEMM + relu + column-sum ----------------
// u = aggx @ W^T + b; zsum[t] += sum_n relu(u_n). Never materializes u.
// Tile: 128 rows per block, full K=128, N=128. 8 warps, each warp: 16 rows x 128 cols.
#define SROW 136                      // padded row stride in bf16 elems (68 words)
#define GEMM_SMEM_BYTES (2*128*SROW*2 + 2*128*4)
#define N_TILES ((N_NODES + 127) / 128)

__global__ __launch_bounds__(256, 2) void gemm_mean_kernel(const float* __restrict__ bias, int t) {
    extern __shared__ __align__(16) char smem[];
    __nv_bfloat16* sA = (__nv_bfloat16*)smem;                  // 128*136
    __nv_bfloat16* sW = sA + 128 * SROW;                       // 128*136
    float* sB  = (float*)(sW + 128 * SROW);                    // 128
    float* red = sB + 128;                                     // 128

    const int tid  = threadIdx.x;
    const int lane = tid & 31;
    const int warp = tid >> 5;        // 0..7
    const int g = lane >> 2;          // 0..7
    const int cc = lane & 3;          // 0..3

    // load W (row-major [j][k] bf16) into padded SMEM
    {
        const int4* Wg = (const int4*)g_Wbf;                   // 16 int4 per row
        #pragma unroll
        for (int i = 0; i < 8; i++) {
            int idx = tid + i * 256;                           // 2048 int4
            int row = idx >> 4, cv = idx & 15;
            *(int4*)(sW + row * SROW + cv * 8) = Wg[idx];
        }
    }
    if (tid < 128) { sB[tid] = bias[tid]; red[tid] = 0.f; }

    const unsigned int* sAw = (const unsigned int*)sA;
    const unsigned int* sWw = (const unsigned int*)sW;
    const int mb = warp * 16;

    for (int tile = blockIdx.x; tile < N_TILES; tile += gridDim.x) {
        __syncthreads();   // sA free / sW+sB ready
        // stage A tile (128 rows x 128 bf16) with zero-fill past N_NODES
        {
            const int4* Ag = (const int4*)g_aggx_bf;
            #pragma unroll
            for (int i = 0; i < 8; i++) {
                int idx = tid + i * 256;                       // 2048 int4
                int lrow = idx >> 4, cv = idx & 15;
                int grow = tile * 128 + lrow;
                int4 v = make_int4(0, 0, 0, 0);
                if (grow < N_NODES) v = Ag[grow * 16 + cv];
                *(int4*)(sA + lrow * SROW + cv * 8) = v;
            }
        }
        __syncthreads();

        float acc[16][4];
        #pragma unroll
        for (int nt = 0; nt < 16; nt++) {
            acc[nt][0] = 0.f; acc[nt][1] = 0.f; acc[nt][2] = 0.f; acc[nt][3] = 0.f;
        }

        #pragma unroll
        for (int ks = 0; ks < 8; ks++) {
            unsigned int a0 = sAw[(mb + g)     * 68 + ks * 8 + cc];
            unsigned int a1 = sAw[(mb + g + 8) * 68 + ks * 8 + cc];
            unsigned int a2 = sAw[(mb + g)     * 68 + ks * 8 + cc + 4];
            unsigned int a3 = sAw[(mb + g + 8) * 68 + ks * 8 + cc + 4];
            #pragma unroll
            for (int nt = 0; nt < 16; nt++) {
                unsigned int b0 = sWw[(nt * 8 + g) * 68 + ks * 8 + cc];
                unsigned int b1 = sWw[(nt * 8 + g) * 68 + ks * 8 + cc + 4];
                asm volatile(
                    "mma.sync.aligned.m16n8k16.row.col.f32.bf16.bf16.f32 "
                    "{%0,%1,%2,%3}, {%4,%5,%6,%7}, {%8,%9}, {%0,%1,%2,%3};\n"
                    : "+f"(acc[nt][0]), "+f"(acc[nt][1]), "+f"(acc[nt][2]), "+f"(acc[nt][3])
                    : "r"(a0), "r"(a1), "r"(a2), "r"(a3), "r"(b0), "r"(b1));
            }
        }

        // epilogue: bias + relu, mask tail rows, reduce over the 16 rows
        int row0 = tile * 128 + mb + g;
        float m0 = (row0 < N_NODES) ? 1.f : 0.f;
        float m1 = (row0 + 8 < N_NODES) ? 1.f : 0.f;
        #pragma unroll
        for (int nt = 0; nt < 16; nt++) {
            float bA = sB[nt * 8 + 2 * cc];
            float bB = sB[nt * 8 + 2 * cc + 1];
            float vA = m0 * fmaxf(acc[nt][0] + bA, 0.f) + m1 * fmaxf(acc[nt][2] + bA, 0.f);
            float vB = m0 * fmaxf(acc[nt][1] + bB, 0.f) + m1 * fmaxf(acc[nt][3] + bB, 0.f);
            #pragma unroll
            for (int o = 4; o < 32; o <<= 1) {
                vA += __shfl_xor_sync(0xffffffff, vA, o);
                vB += __shfl_xor_sync(0xffffffff, vB, o);
            }
            if (lane < 4) {
                atomicAdd(&red[nt * 8 + 2 * lane],     vA);
                atomicAdd(&red[nt * 8 + 2 * lane + 1], vB);
            }
        }
    }

    __syncthreads();
    if (tid < 128) atomicAdd(&g_zsum[t][tid], red[tid]);
}

// ---------------- GRU cell: 384 gate-parallel threads ----------------
__global__ void gru_kernel(const float* __restrict__ Wih, const float* __restrict__ Whh,
                           const float* __restrict__ bih, const float* __restrict__ bhh,
                           int t) {
    __shared__ __align__(16) float z[C];
    __shared__ __align__(16) float hs[C];
    __shared__ float gi[3 * C], gh[3 * C];
    int tid = threadIdx.x;      // 384
    if (tid < C) {
        z[tid]  = g_zsum[t][tid] * (1.f / (float)N_NODES);
        hs[tid] = g_h[tid];
    }
    __syncthreads();

    {
        float ai = bih[tid], ah = bhh[tid];
        const float4* Wi4 = (const float4*)(Wih + tid * C);
        const float4* Wh4 = (const float4*)(Whh + tid * C);
        const float4* z4 = (const float4*)z;
        const float4* h4 = (const float4*)hs;
        #pragma unroll 8
        for (int k = 0; k < 32; k++) {
            float4 w = Wi4[k], v = z4[k];
            ai += w.x * v.x + w.y * v.y + w.z * v.z + w.w * v.w;
            float4 u = Wh4[k], hv = h4[k];
            ah += u.x * hv.x + u.y * hv.y + u.z * hv.z + u.w * hv.w;
        }
        gi[tid] = ai; gh[tid] = ah;
    }
    __syncthreads();

    if (tid < C) {
        float r  = 1.f / (1.f + expf(-(gi[tid] + gh[tid])));
        float zg = 1.f / (1.f + expf(-(gi[C + tid] + gh[C + tid])));
        float ng = tanhf(gi[2 * C + tid] + r * gh[2 * C + tid]);
        g_h[tid] = (1.f - zg) * ng + zg * hs[tid];
    }
}

// ---------------- classifier ----------------
__global__ void cls_kernel(const float* __restrict__ Wc, const float* __restrict__ bc,
                           float* __restrict__ out) {
    int tid = threadIdx.x;
    if (tid < OUT_DIM) {
        float acc = bc[tid];
        const float4* W4 = (const float4*)Wc;
        const float4* h4 = (const float4*)g_h;
        #pragma unroll
        for (int k = 0; k < 32; k++) {
            float4 w = W4[tid * 32 + k], h = h4[k];
            acc += w.x * h.x + w.y * h.y + w.z * h.z + w.w * h.w;
        }
        out[tid] = acc;
    }
}

// ---------------- launch ----------------
extern "C" void kernel_launch(void* const* d_in, const int* in_sizes, int n_in,
                              void* d_out, int out_size) {
    const float* xs    = (const float*)d_in[0];
    const int*   edges = (const int*)  d_in[1];
    const float* Wg    = (const float*)d_in[2];
    const float* bg    = (const float*)d_in[3];
    const float* Wih   = (const float*)d_in[4];
    const float* Whh   = (const float*)d_in[5];
    const float* bih   = (const float*)d_in[6];
    const float* bhh   = (const float*)d_in[7];
    const float* Wc    = (const float*)d_in[8];
    const float* bc    = (const float*)d_in[9];
    float* out = (float*)d_out;

    cudaFuncSetAttribute(gemm_mean_kernel,
                         cudaFuncAttributeMaxDynamicSharedMemorySize, GEMM_SMEM_BYTES);

    init_kernel<<<(T_STEPS * N_NODES + 255) / 256, 256>>>(Wg);

    dim3 egrid((N_EDGES / 4 + 255) / 256, T_STEPS);
    count_all_kernel<<<egrid, 256>>>(edges);
    scan_all_kernel<<<dim3(1, T_STEPS), 1024>>>();
    place_all_kernel<<<egrid, 256>>>(edges);

    for (int t = 0; t < T_STEPS; t++) {
        const float* x = xs + (size_t)t * N_NODES * C;
        gather_kernel<<<(N_NODES * 32 + 255) / 256, 256>>>(x, t);
        gemm_mean_kernel<<<296, 256, GEMM_SMEM_BYTES>>>(bg, t);
        gru_kernel<<<1, 3 * C>>>(Wih, Whh, bih, bhh, t);
    }
    cls_kernel<<<1, 32>>>(Wc, bc, out);
}

// round 3
// speedup vs baseline: 2.6810x; 1.3569x over previous
#include <cuda_runtime.h>
#include <cuda_bf16.h>
#include <math.h>

#define N_NODES 50000
#define N_EDGES 1600000
#define T_STEPS 4
#define C 128
#define OUT_DIM 16
#define CAP 128            // per-node bucket capacity (P[deg>=128 | Poisson(32)] ~ 1e-35)

// ---------------- scratch (device globals; no allocs allowed) ----------------
__device__ int   g_cnt[T_STEPS][N_NODES];
__device__ int   g_bkt[T_STEPS][N_NODES][CAP];                 // 102.4 MB
__device__ __align__(16) __nv_bfloat16 g_x_bf[(size_t)T_STEPS * N_NODES * C];  // 51.2 MB
__device__ __align__(16) __nv_bfloat16 g_aggx_bf[N_NODES * C];
__device__ __align__(16) __nv_bfloat16 g_Wbf[C * C];
__device__ __align__(16) float g_zsum[T_STEPS][C];
__device__ __align__(16) float g_h[C];

// ---------------- init: zero counts/h/zsum, convert W to bf16 ----------------
__global__ void init_kernel(const float* __restrict__ W) {
    int i = blockIdx.x * blockDim.x + threadIdx.x;
    if (i < T_STEPS * N_NODES) ((int*)g_cnt)[i] = 0;
    if (i < C * C) g_Wbf[i] = __float2bfloat16(W[i]);
    if (i < T_STEPS * C) ((float*)g_zsum)[i] = 0.f;
    if (i < C) g_h[i] = 0.f;
}

// ---------------- convert all x to bf16 (one pass, all timesteps) ----------------
__global__ void convert_x_kernel(const float* __restrict__ xs) {
    size_t i = (size_t)blockIdx.x * blockDim.x + threadIdx.x;   // over elems/8
    const size_t total8 = (size_t)T_STEPS * N_NODES * C / 8;
    if (i >= total8) return;
    const float4* x4 = (const float4*)xs;
    float4 a = x4[2 * i], b = x4[2 * i + 1];
    __nv_bfloat162 p0 = __floats2bfloat162_rn(a.x, a.y);
    __nv_bfloat162 p1 = __floats2bfloat162_rn(a.z, a.w);
    __nv_bfloat162 p2 = __floats2bfloat162_rn(b.x, b.y);
    __nv_bfloat162 p3 = __floats2bfloat162_rn(b.z, b.w);
    uint4 o;
    o.x = *(unsigned int*)&p0; o.y = *(unsigned int*)&p1;
    o.z = *(unsigned int*)&p2; o.w = *(unsigned int*)&p3;
    ((uint4*)g_x_bf)[i] = o;
}

// ---------------- one-pass bucketed adjacency build (all timesteps) ----------------
__global__ void build_all_kernel(const int* __restrict__ edges) {
    int t = blockIdx.y;
    int e4 = blockIdx.x * blockDim.x + threadIdx.x;
    const int* base = edges + (size_t)t * 2 * N_EDGES;
    const int4* src4 = (const int4*)base;
    const int4* dst4 = (const int4*)(base + N_EDGES);
    if (e4 < N_EDGES / 4) {
        int4 s = src4[e4];
        int4 d = dst4[e4];
        int p;
        p = atomicAdd(&g_cnt[t][d.x], 1); if (p < CAP) g_bkt[t][d.x][p] = s.x;
        p = atomicAdd(&g_cnt[t][d.y], 1); if (p < CAP) g_bkt[t][d.y][p] = s.y;
        p = atomicAdd(&g_cnt[t][d.z], 1); if (p < CAP) g_bkt[t][d.z][p] = s.z;
        p = atomicAdd(&g_cnt[t][d.w], 1); if (p < CAP) g_bkt[t][d.w][p] = s.w;
    }
}

// ---------------- gather: warp per node, bf16 reads, fp32 accum ----------------
__device__ __forceinline__ float4 bf8_to_f4sum(uint2 v) {
    __nv_bfloat162 b0 = *(__nv_bfloat162*)&v.x;
    __nv_bfloat162 b1 = *(__nv_bfloat162*)&v.y;
    float2 f0 = __bfloat1622float2(b0);
    float2 f1 = __bfloat1622float2(b1);
    return make_float4(f0.x, f0.y, f1.x, f1.y);
}

__global__ __launch_bounds__(256) void gather_kernel(int t) {
    int node = (blockIdx.x * blockDim.x + threadIdx.x) >> 5;
    int lane = threadIdx.x & 31;
    if (node >= N_NODES) return;

    const uint2* __restrict__ xb = ((const uint2*)g_x_bf) + (size_t)t * N_NODES * 32;
    const int* __restrict__ bkt = g_bkt[t][node];

    float4 acc = bf8_to_f4sum(xb[node * 32 + lane]);   // self loop
    int deg = min(g_cnt[t][node], CAP);

    int i = 0;
    for (; i + 3 < deg; i += 4) {
        int s0 = bkt[i], s1 = bkt[i + 1], s2 = bkt[i + 2], s3 = bkt[i + 3];
        float4 a = bf8_to_f4sum(xb[s0 * 32 + lane]);
        float4 b = bf8_to_f4sum(xb[s1 * 32 + lane]);
        float4 c = bf8_to_f4sum(xb[s2 * 32 + lane]);
        float4 d = bf8_to_f4sum(xb[s3 * 32 + lane]);
        acc.x += (a.x + b.x) + (c.x + d.x);
        acc.y += (a.y + b.y) + (c.y + d.y);
        acc.z += (a.z + b.z) + (c.z + d.z);
        acc.w += (a.w + b.w) + (c.w + d.w);
    }
    for (; i < deg; i++) {
        float4 a = bf8_to_f4sum(xb[bkt[i] * 32 + lane]);
        acc.x += a.x; acc.y += a.y; acc.z += a.z; acc.w += a.w;
    }

    float inv = 1.f / (float)(deg + 1);
    __nv_bfloat162 p0 = __floats2bfloat162_rn(acc.x * inv, acc.y * inv);
    __nv_bfloat162 p1 = __floats2bfloat162_rn(acc.z * inv, acc.w * inv);
    uint2 o;
    o.x = *(unsigned int*)&p0;
    o.y = *(unsigned int*)&p1;
    ((uint2*)g_aggx_bf)[node * 32 + lane] = o;
}

// ---------------- bf16 tensor-core GEMM + relu + column-sum ----------------
#define SROW 136
#define GEMM_SMEM_BYTES (2*128*SROW*2 + 2*128*4)
#define N_TILES ((N_NODES + 127) / 128)

__global__ __launch_bounds__(256, 2) void gemm_mean_kernel(const float* __restrict__ bias, int t) {
    extern __shared__ __align__(16) char smem[];
    __nv_bfloat16* sA = (__nv_bfloat16*)smem;                  // 128*136
    __nv_bfloat16* sW = sA + 128 * SROW;                       // 128*136
    float* sB  = (float*)(sW + 128 * SROW);                    // 128
    float* red = sB + 128;                                     // 128

    const int tid  = threadIdx.x;
    const int lane = tid & 31;
    const int warp = tid >> 5;
    const int g = lane >> 2;
    const int cc = lane & 3;

    {
        const int4* Wg = (const int4*)g_Wbf;
        #pragma unroll
        for (int i = 0; i < 8; i++) {
            int idx = tid + i * 256;
            int row = idx >> 4, cv = idx & 15;
            *(int4*)(sW + row * SROW + cv * 8) = Wg[idx];
        }
    }
    if (tid < 128) { sB[tid] = bias[tid]; red[tid] = 0.f; }

    const unsigned int* sAw = (const unsigned int*)sA;
    const unsigned int* sWw = (const unsigned int*)sW;
    const int mb = warp * 16;

    for (int tile = blockIdx.x; tile < N_TILES; tile += gridDim.x) {
        __syncthreads();
        {
            const int4* Ag = (const int4*)g_aggx_bf;
            #pragma unroll
            for (int i = 0; i < 8; i++) {
                int idx = tid + i * 256;
                int lrow = idx >> 4, cv = idx & 15;
                int grow = tile * 128 + lrow;
                int4 v = make_int4(0, 0, 0, 0);
                if (grow < N_NODES) v = Ag[grow * 16 + cv];
                *(int4*)(sA + lrow * SROW + cv * 8) = v;
            }
        }
        __syncthreads();

        float acc[16][4];
        #pragma unroll
        for (int nt = 0; nt < 16; nt++) {
            acc[nt][0] = 0.f; acc[nt][1] = 0.f; acc[nt][2] = 0.f; acc[nt][3] = 0.f;
        }

        #pragma unroll
        for (int ks = 0; ks < 8; ks++) {
            unsigned int a0 = sAw[(mb + g)     * 68 + ks * 8 + cc];
            unsigned int a1 = sAw[(mb + g + 8) * 68 + ks * 8 + cc];
            unsigned int a2 = sAw[(mb + g)     * 68 + ks * 8 + cc + 4];
            unsigned int a3 = sAw[(mb + g + 8) * 68 + ks * 8 + cc + 4];
            #pragma unroll
            for (int nt = 0; nt < 16; nt++) {
                unsigned int b0 = sWw[(nt * 8 + g) * 68 + ks * 8 + cc];
                unsigned int b1 = sWw[(nt * 8 + g) * 68 + ks * 8 + cc + 4];
                asm volatile(
                    "mma.sync.aligned.m16n8k16.row.col.f32.bf16.bf16.f32 "
                    "{%0,%1,%2,%3}, {%4,%5,%6,%7}, {%8,%9}, {%0,%1,%2,%3};\n"
                    : "+f"(acc[nt][0]), "+f"(acc[nt][1]), "+f"(acc[nt][2]), "+f"(acc[nt][3])
                    : "r"(a0), "r"(a1), "r"(a2), "r"(a3), "r"(b0), "r"(b1));
            }
        }

        int row0 = tile * 128 + mb + g;
        float m0 = (row0 < N_NODES) ? 1.f : 0.f;
        float m1 = (row0 + 8 < N_NODES) ? 1.f : 0.f;
        #pragma unroll
        for (int nt = 0; nt < 16; nt++) {
            float bA = sB[nt * 8 + 2 * cc];
            float bB = sB[nt * 8 + 2 * cc + 1];
            float vA = m0 * fmaxf(acc[nt][0] + bA, 0.f) + m1 * fmaxf(acc[nt][2] + bA, 0.f);
            float vB = m0 * fmaxf(acc[nt][1] + bB, 0.f) + m1 * fmaxf(acc[nt][3] + bB, 0.f);
            #pragma unroll
            for (int o = 4; o < 32; o <<= 1) {
                vA += __shfl_xor_sync(0xffffffff, vA, o);
                vB += __shfl_xor_sync(0xffffffff, vB, o);
            }
            if (lane < 4) {
                atomicAdd(&red[nt * 8 + 2 * lane],     vA);
                atomicAdd(&red[nt * 8 + 2 * lane + 1], vB);
            }
        }
    }

    __syncthreads();
    if (tid < 128) atomicAdd(&g_zsum[t][tid], red[tid]);
}

// ---------------- GRU cell: 384 gate-parallel threads ----------------
__global__ void gru_kernel(const float* __restrict__ Wih, const float* __restrict__ Whh,
                           const float* __restrict__ bih, const float* __restrict__ bhh,
                           int t) {
    __shared__ __align__(16) float z[C];
    __shared__ __align__(16) float hs[C];
    __shared__ float gi[3 * C], gh[3 * C];
    int tid = threadIdx.x;      // 384
    if (tid < C) {
        z[tid]  = g_zsum[t][tid] * (1.f / (float)N_NODES);
        hs[tid] = g_h[tid];
    }
    __syncthreads();

    {
        float ai = bih[tid], ah = bhh[tid];
        const float4* Wi4 = (const float4*)(Wih + tid * C);
        const float4* Wh4 = (const float4*)(Whh + tid * C);
        const float4* z4 = (const float4*)z;
        const float4* h4 = (const float4*)hs;
        #pragma unroll 8
        for (int k = 0; k < 32; k++) {
            float4 w = Wi4[k], v = z4[k];
            ai += w.x * v.x + w.y * v.y + w.z * v.z + w.w * v.w;
            float4 u = Wh4[k], hv = h4[k];
            ah += u.x * hv.x + u.y * hv.y + u.z * hv.z + u.w * hv.w;
        }
        gi[tid] = ai; gh[tid] = ah;
    }
    __syncthreads();

    if (tid < C) {
        float r  = 1.f / (1.f + expf(-(gi[tid] + gh[tid])));
        float zg = 1.f / (1.f + expf(-(gi[C + tid] + gh[C + tid])));
        float ng = tanhf(gi[2 * C + tid] + r * gh[2 * C + tid]);
        g_h[tid] = (1.f - zg) * ng + zg * hs[tid];
    }
}

// ---------------- classifier ----------------
__global__ void cls_kernel(const float* __restrict__ Wc, const float* __restrict__ bc,
                           float* __restrict__ out) {
    int tid = threadIdx.x;
    if (tid < OUT_DIM) {
        float acc = bc[tid];
        const float4* W4 = (const float4*)Wc;
        const float4* h4 = (const float4*)g_h;
        #pragma unroll
        for (int k = 0; k < 32; k++) {
            float4 w = W4[tid * 32 + k], h = h4[k];
            acc += w.x * h.x + w.y * h.y + w.z * h.z + w.w * h.w;
        }
        out[tid] = acc;
    }
}

// ---------------- launch ----------------
extern "C" void kernel_launch(void* const* d_in, const int* in_sizes, int n_in,
                              void* d_out, int out_size) {
    const float* xs    = (const float*)d_in[0];
    const int*   edges = (const int*)  d_in[1];
    const float* Wg    = (const float*)d_in[2];
    const float* bg    = (const float*)d_in[3];
    const float* Wih   = (const float*)d_in[4];
    const float* Whh   = (const float*)d_in[5];
    const float* bih   = (const float*)d_in[6];
    const float* bhh   = (const float*)d_in[7];
    const float* Wc    = (const float*)d_in[8];
    const float* bc    = (const float*)d_in[9];
    float* out = (float*)d_out;

    cudaFuncSetAttribute(gemm_mean_kernel,
                         cudaFuncAttributeMaxDynamicSharedMemorySize, GEMM_SMEM_BYTES);

    init_kernel<<<(T_STEPS * N_NODES + 255) / 256, 256>>>(Wg);
    convert_x_kernel<<<(int)(((size_t)T_STEPS * N_NODES * C / 8 + 255) / 256), 256>>>(xs);

    dim3 egrid((N_EDGES / 4 + 255) / 256, T_STEPS);
    build_all_kernel<<<egrid, 256>>>(edges);

    for (int t = 0; t < T_STEPS; t++) {
        gather_kernel<<<(N_NODES * 32 + 255) / 256, 256>>>(t);
        gemm_mean_kernel<<<296, 256, GEMM_SMEM_BYTES>>>(bg, t);
        gru_kernel<<<1, 3 * C>>>(Wih, Whh, bih, bhh, t);
    }
    cls_kernel<<<1, 32>>>(Wc, bc, out);
}

// round 4
// speedup vs baseline: 2.6981x; 1.0064x over previous
#include <cuda_runtime.h>
#include <cuda_bf16.h>
#include <math.h>

#define N_NODES 50000
#define N_EDGES 1600000
#define T_STEPS 4
#define C 128
#define OUT_DIM 16
#define CAP 128            // P[deg>=128 | Poisson(32)] ~ 1e-35

// ---------------- scratch (device globals; no allocs allowed) ----------------
__device__ int   g_cnt[T_STEPS][N_NODES];
__device__ int   g_bkt[T_STEPS][N_NODES][CAP];                 // 102.4 MB
__device__ __align__(16) __nv_bfloat16 g_x_bf[(size_t)T_STEPS * N_NODES * C];  // 51.2 MB
__device__ __align__(16) __nv_bfloat16 g_aggx_bf[N_NODES * C]; // PERMUTED word order
__device__ __align__(16) __nv_bfloat16 g_Wbf[C * C];           // PERMUTED word order
__device__ __align__(16) float g_zsum[T_STEPS][C];
__device__ __align__(16) float g_h[C];

// word permutation within a 64-word (128 bf16) K-row, so that the 4 mma
// fragment words of a ks-pair are 16B-contiguous for LDS.128.
__device__ __forceinline__ int permw(int w) {
    int ks = w >> 3, cc = w & 3, half = (w >> 2) & 1;
    return (ks >> 1) * 16 + cc * 4 + (ks & 1) * 2 + half;
}

// ---------------- init: zero counts/h/zsum, convert W to bf16 (permuted) ----------------
__global__ void init_kernel(const float* __restrict__ W) {
    int i = blockIdx.x * blockDim.x + threadIdx.x;
    if (i < T_STEPS * N_NODES) ((int*)g_cnt)[i] = 0;
    if (i < C * C) {
        int j = i >> 7, k = i & 127;
        g_Wbf[j * 128 + permw(k >> 1) * 2 + (k & 1)] = __float2bfloat16(W[i]);
    }
    if (i < T_STEPS * C) ((float*)g_zsum)[i] = 0.f;
    if (i < C) g_h[i] = 0.f;
}

// ---------------- fused: convert x to bf16  +  bucketed adjacency build ----------------
#define CONV_BLOCKS 12500            // (T*N*C/8) / 256
#define BUILD_BX ((N_EDGES / 4 + 255) / 256)   // 1563
__global__ void prep_kernel(const float* __restrict__ xs, const int* __restrict__ edges) {
    int bid = blockIdx.x;
    if (bid < CONV_BLOCKS) {
        size_t i = (size_t)bid * blockDim.x + threadIdx.x;   // over elems/8
        const float4* x4 = (const float4*)xs;
        float4 a = x4[2 * i], b = x4[2 * i + 1];
        __nv_bfloat162 p0 = __floats2bfloat162_rn(a.x, a.y);
        __nv_bfloat162 p1 = __floats2bfloat162_rn(a.z, a.w);
        __nv_bfloat162 p2 = __floats2bfloat162_rn(b.x, b.y);
        __nv_bfloat162 p3 = __floats2bfloat162_rn(b.z, b.w);
        uint4 o;
        o.x = *(unsigned int*)&p0; o.y = *(unsigned int*)&p1;
        o.z = *(unsigned int*)&p2; o.w = *(unsigned int*)&p3;
        ((uint4*)g_x_bf)[i] = o;
    } else {
        int be = bid - CONV_BLOCKS;
        int t = be / BUILD_BX;
        int e4 = (be - t * BUILD_BX) * blockDim.x + threadIdx.x;
        const int* base = edges + (size_t)t * 2 * N_EDGES;
        const int4* src4 = (const int4*)base;
        const int4* dst4 = (const int4*)(base + N_EDGES);
        if (e4 < N_EDGES / 4) {
            int4 s = src4[e4];
            int4 d = dst4[e4];
            int p;
            p = atomicAdd(&g_cnt[t][d.x], 1); if (p < CAP) g_bkt[t][d.x][p] = s.x;
            p = atomicAdd(&g_cnt[t][d.y], 1); if (p < CAP) g_bkt[t][d.y][p] = s.y;
            p = atomicAdd(&g_cnt[t][d.z], 1); if (p < CAP) g_bkt[t][d.z][p] = s.z;
            p = atomicAdd(&g_cnt[t][d.w], 1); if (p < CAP) g_bkt[t][d.w][p] = s.w;
        }
    }
}

// ---------------- gather: warp per node, bf16 HADD2 chunk trees, fp32 accum ----------------
__device__ __forceinline__ float4 bf8_to_f4(uint2 v) {
    float2 f0 = __bfloat1622float2(*(__nv_bfloat162*)&v.x);
    float2 f1 = __bfloat1622float2(*(__nv_bfloat162*)&v.y);
    return make_float4(f0.x, f0.y, f1.x, f1.y);
}
__device__ __forceinline__ unsigned int hadd2b(unsigned int a, unsigned int b) {
    __nv_bfloat162 r = __hadd2(*(__nv_bfloat162*)&a, *(__nv_bfloat162*)&b);
    return *(unsigned int*)&r;
}

__global__ __launch_bounds__(256) void gather_kernel(int t) {
    int node = (blockIdx.x * blockDim.x + threadIdx.x) >> 5;
    int lane = threadIdx.x & 31;
    if (node >= N_NODES) return;

    const uint2* __restrict__ xb = ((const uint2*)g_x_bf) + (size_t)t * N_NODES * 32;
    const int* __restrict__ bkt = g_bkt[t][node];

    float4 acc = bf8_to_f4(xb[node * 32 + lane]);   // self loop (fp32)
    int deg = min(g_cnt[t][node], CAP);

    int i = 0;
    for (; i + 3 < deg; i += 4) {
        int s0 = bkt[i], s1 = bkt[i + 1], s2 = bkt[i + 2], s3 = bkt[i + 3];
        uint2 a = xb[s0 * 32 + lane];
        uint2 b = xb[s1 * 32 + lane];
        uint2 c = xb[s2 * 32 + lane];
        uint2 d = xb[s3 * 32 + lane];
        unsigned int sx = hadd2b(hadd2b(a.x, b.x), hadd2b(c.x, d.x));
        unsigned int sy = hadd2b(hadd2b(a.y, b.y), hadd2b(c.y, d.y));
        float2 f0 = __bfloat1622float2(*(__nv_bfloat162*)&sx);
        float2 f1 = __bfloat1622float2(*(__nv_bfloat162*)&sy);
        acc.x += f0.x; acc.y += f0.y; acc.z += f1.x; acc.w += f1.y;
    }
    for (; i < deg; i++) {
        float4 a = bf8_to_f4(xb[bkt[i] * 32 + lane]);
        acc.x += a.x; acc.y += a.y; acc.z += a.z; acc.w += a.w;
    }

    float inv = 1.f / (float)(deg + 1);
    __nv_bfloat162 p0 = __floats2bfloat162_rn(acc.x * inv, acc.y * inv);
    __nv_bfloat162 p1 = __floats2bfloat162_rn(acc.z * inv, acc.w * inv);
    // permuted word positions (lane covers orig words 2*lane, 2*lane+1)
    unsigned int* row = ((unsigned int*)g_aggx_bf) + node * 64;
    row[permw(2 * lane)]     = *(unsigned int*)&p0;
    row[permw(2 * lane + 1)] = *(unsigned int*)&p1;
}

// ---------------- bf16 tensor-core GEMM + relu + column-sum (LDS.128 mainloop) ----------------
#define SROWW 80                         // padded row stride in 32-bit words (320 B)
#define GEMM_SMEM_BYTES (2*128*SROWW*4 + 2*128*4)
#define N_TILES ((N_NODES + 127) / 128)

__global__ __launch_bounds__(256, 2) void gemm_mean_kernel(const float* __restrict__ bias, int t) {
    extern __shared__ __align__(16) char smem[];
    unsigned int* sAw = (unsigned int*)smem;               // 128 x 80 words
    unsigned int* sWw = sAw + 128 * SROWW;                 // 128 x 80 words
    float* sB  = (float*)(sWw + 128 * SROWW);              // 128
    float* red = sB + 128;                                 // 128

    const int tid  = threadIdx.x;
    const int lane = tid & 31;
    const int warp = tid >> 5;
    const int g = lane >> 2;
    const int cc = lane & 3;

    {   // stage permuted W: gmem int4 chunk cv -> smem words row*80 + cv*4
        const int4* Wg = (const int4*)g_Wbf;
        #pragma unroll
        for (int i = 0; i < 8; i++) {
            int idx = tid + i * 256;
            int row = idx >> 4, cv = idx & 15;
            *(int4*)&sWw[row * SROWW + cv * 4] = Wg[idx];
        }
    }
    if (tid < 128) { sB[tid] = bias[tid]; red[tid] = 0.f; }

    const int mb = warp * 16;

    for (int tile = blockIdx.x; tile < N_TILES; tile += gridDim.x) {
        __syncthreads();
        {
            const int4* Ag = (const int4*)g_aggx_bf;
            #pragma unroll
            for (int i = 0; i < 8; i++) {
                int idx = tid + i * 256;
                int lrow = idx >> 4, cv = idx & 15;
                int grow = tile * 128 + lrow;
                int4 v = make_int4(0, 0, 0, 0);
                if (grow < N_NODES) v = Ag[grow * 16 + cv];
                *(int4*)&sAw[lrow * SROWW + cv * 4] = v;
            }
        }
        __syncthreads();

        float acc[16][4];
        #pragma unroll
        for (int nt = 0; nt < 16; nt++) {
            acc[nt][0] = 0.f; acc[nt][1] = 0.f; acc[nt][2] = 0.f; acc[nt][3] = 0.f;
        }

        #pragma unroll
        for (int kk = 0; kk < 4; kk++) {     // ks-pair
            uint4 qa0 = *(uint4*)&sAw[(mb + g)     * SROWW + kk * 16 + cc * 4];
            uint4 qa1 = *(uint4*)&sAw[(mb + g + 8) * SROWW + kk * 16 + cc * 4];
            #pragma unroll
            for (int nt = 0; nt < 16; nt++) {
                uint4 qb = *(uint4*)&sWw[(nt * 8 + g) * SROWW + kk * 16 + cc * 4];
                asm volatile(
                    "mma.sync.aligned.m16n8k16.row.col.f32.bf16.bf16.f32 "
                    "{%0,%1,%2,%3}, {%4,%5,%6,%7}, {%8,%9}, {%0,%1,%2,%3};\n"
                    : "+f"(acc[nt][0]), "+f"(acc[nt][1]), "+f"(acc[nt][2]), "+f"(acc[nt][3])
                    : "r"(qa0.x), "r"(qa1.x), "r"(qa0.y), "r"(qa1.y),
                      "r"(qb.x), "r"(qb.y));
                asm volatile(
                    "mma.sync.aligned.m16n8k16.row.col.f32.bf16.bf16.f32 "
                    "{%0,%1,%2,%3}, {%4,%5,%6,%7}, {%8,%9}, {%0,%1,%2,%3};\n"
                    : "+f"(acc[nt][0]), "+f"(acc[nt][1]), "+f"(acc[nt][2]), "+f"(acc[nt][3])
                    : "r"(qa0.z), "r"(qa1.z), "r"(qa0.w), "r"(qa1.w),
                      "r"(qb.z), "r"(qb.w));
            }
        }

        int row0 = tile * 128 + mb + g;
        float m0 = (row0 < N_NODES) ? 1.f : 0.f;
        float m1 = (row0 + 8 < N_NODES) ? 1.f : 0.f;
        #pragma unroll
        for (int nt = 0; nt < 16; nt++) {
            float bA = sB[nt * 8 + 2 * cc];
            float bB = sB[nt * 8 + 2 * cc + 1];
            float vA = m0 * fmaxf(acc[nt][0] + bA, 0.f) + m1 * fmaxf(acc[nt][2] + bA, 0.f);
            float vB = m0 * fmaxf(acc[nt][1] + bB, 0.f) + m1 * fmaxf(acc[nt][3] + bB, 0.f);
            #pragma unroll
            for (int o = 4; o < 32; o <<= 1) {
                vA += __shfl_xor_sync(0xffffffff, vA, o);
                vB += __shfl_xor_sync(0xffffffff, vB, o);
            }
            if (lane < 4) {
                atomicAdd(&red[nt * 8 + 2 * lane],     vA);
                atomicAdd(&red[nt * 8 + 2 * lane + 1], vB);
            }
        }
    }

    __syncthreads();
    if (tid < 128) atomicAdd(&g_zsum[t][tid], red[tid]);
}

// ---------------- GRU cell: 384 gate-parallel threads ----------------
__global__ void gru_kernel(const float* __restrict__ Wih, const float* __restrict__ Whh,
                           const float* __restrict__ bih, const float* __restrict__ bhh,
                           int t) {
    __shared__ __align__(16) float z[C];
    __shared__ __align__(16) float hs[C];
    __shared__ float gi[3 * C], gh[3 * C];
    int tid = threadIdx.x;      // 384
    if (tid < C) {
        z[tid]  = g_zsum[t][tid] * (1.f / (float)N_NODES);
        hs[tid] = g_h[tid];
    }
    __syncthreads();

    {
        float ai = bih[tid], ah = bhh[tid];
        const float4* Wi4 = (const float4*)(Wih + tid * C);
        const float4* Wh4 = (const float4*)(Whh + tid * C);
        const float4* z4 = (const float4*)z;
        const float4* h4 = (const float4*)hs;
        #pragma unroll 8
        for (int k = 0; k < 32; k++) {
            float4 w = Wi4[k], v = z4[k];
            ai += w.x * v.x + w.y * v.y + w.z * v.z + w.w * v.w;
            float4 u = Wh4[k], hv = h4[k];
            ah += u.x * hv.x + u.y * hv.y + u.z * hv.z + u.w * hv.w;
        }
        gi[tid] = ai; gh[tid] = ah;
    }
    __syncthreads();

    if (tid < C) {
        float r  = 1.f / (1.f + expf(-(gi[tid] + gh[tid])));
        float zg = 1.f / (1.f + expf(-(gi[C + tid] + gh[C + tid])));
        float ng = tanhf(gi[2 * C + tid] + r * gh[2 * C + tid]);
        g_h[tid] = (1.f - zg) * ng + zg * hs[tid];
    }
}

// ---------------- classifier ----------------
__global__ void cls_kernel(const float* __restrict__ Wc, const float* __restrict__ bc,
                           float* __restrict__ out) {
    int tid = threadIdx.x;
    if (tid < OUT_DIM) {
        float acc = bc[tid];
        const float4* W4 = (const float4*)Wc;
        const float4* h4 = (const float4*)g_h;
        #pragma unroll
        for (int k = 0; k < 32; k++) {
            float4 w = W4[tid * 32 + k], h = h4[k];
            acc += w.x * h.x + w.y * h.y + w.z * h.z + w.w * h.w;
        }
        out[tid] = acc;
    }
}

// ---------------- launch ----------------
extern "C" void kernel_launch(void* const* d_in, const int* in_sizes, int n_in,
                              void* d_out, int out_size) {
    const float* xs    = (const float*)d_in[0];
    const int*   edges = (const int*)  d_in[1];
    const float* Wg    = (const float*)d_in[2];
    const float* bg    = (const float*)d_in[3];
    const float* Wih   = (const float*)d_in[4];
    const float* Whh   = (const float*)d_in[5];
    const float* bih   = (const float*)d_in[6];
    const float* bhh   = (const float*)d_in[7];
    const float* Wc    = (const float*)d_in[8];
    const float* bc    = (const float*)d_in[9];
    float* out = (float*)d_out;

    cudaFuncSetAttribute(gemm_mean_kernel,
                         cudaFuncAttributeMaxDynamicSharedMemorySize, GEMM_SMEM_BYTES);

    init_kernel<<<(T_STEPS * N_NODES + 255) / 256, 256>>>(Wg);
    prep_kernel<<<CONV_BLOCKS + BUILD_BX * T_STEPS, 256>>>(xs, edges);

    for (int t = 0; t < T_STEPS; t++) {
        gather_kernel<<<(N_NODES * 32 + 255) / 256, 256>>>(t);
        gemm_mean_kernel<<<296, 256, GEMM_SMEM_BYTES>>>(bg, t);
        gru_kernel<<<1, 3 * C>>>(Wih, Whh, bih, bhh, t);
    }
    cls_kernel<<<1, 32>>>(Wc, bc, out);
}

// round 5
// speedup vs baseline: 2.8545x; 1.0580x over previous
#include <cuda_runtime.h>
#include <cuda_bf16.h>
#include <math.h>

#define N_NODES 50000
#define N_EDGES 1600000
#define T_STEPS 4
#define C 128
#define OUT_DIM 16
#define CAP 128            // P[deg>=128 | Poisson(32)] ~ 1e-35

// ---------------- scratch (device globals; no allocs allowed) ----------------
__device__ int   g_cnt[T_STEPS][N_NODES];
__device__ int   g_bkt[T_STEPS][N_NODES][CAP];                 // 102.4 MB
__device__ __align__(16) __nv_bfloat16 g_x_bf[(size_t)T_STEPS * N_NODES * C];  // 51.2 MB
__device__ __align__(16) __nv_bfloat16 g_aggx_bf[T_STEPS][N_NODES * C];  // 51.2 MB, PERMUTED
__device__ __align__(16) __nv_bfloat16 g_Wbf[C * C];           // PERMUTED word order
__device__ __align__(16) float g_zsum[T_STEPS][C];
__device__ __align__(16) float g_h[C];

// word permutation within a 64-word (128 bf16) K-row: the 4 mma fragment words
// of a ks-pair are 16B-contiguous for LDS.128.
__device__ __forceinline__ int permw(int w) {
    int ks = w >> 3, cc = w & 3, half = (w >> 2) & 1;
    return (ks >> 1) * 16 + cc * 4 + (ks & 1) * 2 + half;
}

// ---------------- init: zero counts/h/zsum, convert W to bf16 (permuted) ----------------
__global__ void init_kernel(const float* __restrict__ W) {
    int i = blockIdx.x * blockDim.x + threadIdx.x;
    if (i < T_STEPS * N_NODES) ((int*)g_cnt)[i] = 0;
    if (i < C * C) {
        int j = i >> 7, k = i & 127;
        g_Wbf[j * 128 + permw(k >> 1) * 2 + (k & 1)] = __float2bfloat16(W[i]);
    }
    if (i < T_STEPS * C) ((float*)g_zsum)[i] = 0.f;
    if (i < C) g_h[i] = 0.f;
}

// ---------------- convert all x to bf16 ----------------
__global__ void convert_x_kernel(const float* __restrict__ xs) {
    size_t i = (size_t)blockIdx.x * blockDim.x + threadIdx.x;   // over elems/8
    const size_t total8 = (size_t)T_STEPS * N_NODES * C / 8;
    if (i >= total8) return;
    const float4* x4 = (const float4*)xs;
    float4 a = x4[2 * i], b = x4[2 * i + 1];
    __nv_bfloat162 p0 = __floats2bfloat162_rn(a.x, a.y);
    __nv_bfloat162 p1 = __floats2bfloat162_rn(a.z, a.w);
    __nv_bfloat162 p2 = __floats2bfloat162_rn(b.x, b.y);
    __nv_bfloat162 p3 = __floats2bfloat162_rn(b.z, b.w);
    uint4 o;
    o.x = *(unsigned int*)&p0; o.y = *(unsigned int*)&p1;
    o.z = *(unsigned int*)&p2; o.w = *(unsigned int*)&p3;
    ((uint4*)g_x_bf)[i] = o;
}

// ---------------- bucketed adjacency build (one timestep) ----------------
__global__ void build_kernel(const int* __restrict__ edges, int t) {
    int e4 = blockIdx.x * blockDim.x + threadIdx.x;
    const int* base = edges + (size_t)t * 2 * N_EDGES;
    const int4* src4 = (const int4*)base;
    const int4* dst4 = (const int4*)(base + N_EDGES);
    if (e4 < N_EDGES / 4) {
        int4 s = src4[e4];
        int4 d = dst4[e4];
        int p;
        p = atomicAdd(&g_cnt[t][d.x], 1); if (p < CAP) g_bkt[t][d.x][p] = s.x;
        p = atomicAdd(&g_cnt[t][d.y], 1); if (p < CAP) g_bkt[t][d.y][p] = s.y;
        p = atomicAdd(&g_cnt[t][d.z], 1); if (p < CAP) g_bkt[t][d.z][p] = s.z;
        p = atomicAdd(&g_cnt[t][d.w], 1); if (p < CAP) g_bkt[t][d.w][p] = s.w;
    }
}

// ---------------- gather: warp per node, bf16 HADD2 chunk trees, fp32 accum ----------------
__device__ __forceinline__ float4 bf8_to_f4(uint2 v) {
    float2 f0 = __bfloat1622float2(*(__nv_bfloat162*)&v.x);
    float2 f1 = __bfloat1622float2(*(__nv_bfloat162*)&v.y);
    return make_float4(f0.x, f0.y, f1.x, f1.y);
}
__device__ __forceinline__ unsigned int hadd2b(unsigned int a, unsigned int b) {
    __nv_bfloat162 r = __hadd2(*(__nv_bfloat162*)&a, *(__nv_bfloat162*)&b);
    return *(unsigned int*)&r;
}

__global__ __launch_bounds__(256) void gather_kernel(int t) {
    int node = (blockIdx.x * blockDim.x + threadIdx.x) >> 5;
    int lane = threadIdx.x & 31;
    if (node >= N_NODES) return;

    const uint2* __restrict__ xb = ((const uint2*)g_x_bf) + (size_t)t * N_NODES * 32;
    const int* __restrict__ bkt = g_bkt[t][node];

    float4 acc = bf8_to_f4(xb[node * 32 + lane]);   // self loop (fp32)
    int deg = min(g_cnt[t][node], CAP);

    int i = 0;
    for (; i + 3 < deg; i += 4) {
        int s0 = bkt[i], s1 = bkt[i + 1], s2 = bkt[i + 2], s3 = bkt[i + 3];
        uint2 a = xb[s0 * 32 + lane];
        uint2 b = xb[s1 * 32 + lane];
        uint2 c = xb[s2 * 32 + lane];
        uint2 d = xb[s3 * 32 + lane];
        unsigned int sx = hadd2b(hadd2b(a.x, b.x), hadd2b(c.x, d.x));
        unsigned int sy = hadd2b(hadd2b(a.y, b.y), hadd2b(c.y, d.y));
        float2 f0 = __bfloat1622float2(*(__nv_bfloat162*)&sx);
        float2 f1 = __bfloat1622float2(*(__nv_bfloat162*)&sy);
        acc.x += f0.x; acc.y += f0.y; acc.z += f1.x; acc.w += f1.y;
    }
    for (; i < deg; i++) {
        float4 a = bf8_to_f4(xb[bkt[i] * 32 + lane]);
        acc.x += a.x; acc.y += a.y; acc.z += a.z; acc.w += a.w;
    }

    float inv = 1.f / (float)(deg + 1);
    __nv_bfloat162 p0 = __floats2bfloat162_rn(acc.x * inv, acc.y * inv);
    __nv_bfloat162 p1 = __floats2bfloat162_rn(acc.z * inv, acc.w * inv);
    unsigned int* row = ((unsigned int*)g_aggx_bf[t]) + node * 64;
    row[permw(2 * lane)]     = *(unsigned int*)&p0;
    row[permw(2 * lane + 1)] = *(unsigned int*)&p1;
}

// ---------------- bf16 tensor-core GEMM + relu + column-sum (LDS.128 mainloop) ----------------
#define SROWW 80                         // padded row stride in 32-bit words
#define GEMM_SMEM_BYTES (2*128*SROWW*4 + 2*128*4)
#define N_TILES ((N_NODES + 127) / 128)

__global__ __launch_bounds__(256, 2) void gemm_mean_kernel(const float* __restrict__ bias, int t) {
    extern __shared__ __align__(16) char smem[];
    unsigned int* sAw = (unsigned int*)smem;               // 128 x 80 words
    unsigned int* sWw = sAw + 128 * SROWW;                 // 128 x 80 words
    float* sB  = (float*)(sWw + 128 * SROWW);              // 128
    float* red = sB + 128;                                 // 128

    const int tid  = threadIdx.x;
    const int lane = tid & 31;
    const int warp = tid >> 5;
    const int g = lane >> 2;
    const int cc = lane & 3;

    {
        const int4* Wg = (const int4*)g_Wbf;
        #pragma unroll
        for (int i = 0; i < 8; i++) {
            int idx = tid + i * 256;
            int row = idx >> 4, cv = idx & 15;
            *(int4*)&sWw[row * SROWW + cv * 4] = Wg[idx];
        }
    }
    if (tid < 128) { sB[tid] = bias[tid]; red[tid] = 0.f; }

    const int mb = warp * 16;

    for (int tile = blockIdx.x; tile < N_TILES; tile += gridDim.x) {
        __syncthreads();
        {
            const int4* Ag = (const int4*)g_aggx_bf[t];
            #pragma unroll
            for (int i = 0; i < 8; i++) {
                int idx = tid + i * 256;
                int lrow = idx >> 4, cv = idx & 15;
                int grow = tile * 128 + lrow;
                int4 v = make_int4(0, 0, 0, 0);
                if (grow < N_NODES) v = Ag[grow * 16 + cv];
                *(int4*)&sAw[lrow * SROWW + cv * 4] = v;
            }
        }
        __syncthreads();

        float acc[16][4];
        #pragma unroll
        for (int nt = 0; nt < 16; nt++) {
            acc[nt][0] = 0.f; acc[nt][1] = 0.f; acc[nt][2] = 0.f; acc[nt][3] = 0.f;
        }

        #pragma unroll
        for (int kk = 0; kk < 4; kk++) {
            uint4 qa0 = *(uint4*)&sAw[(mb + g)     * SROWW + kk * 16 + cc * 4];
            uint4 qa1 = *(uint4*)&sAw[(mb + g + 8) * SROWW + kk * 16 + cc * 4];
            #pragma unroll
            for (int nt = 0; nt < 16; nt++) {
                uint4 qb = *(uint4*)&sWw[(nt * 8 + g) * SROWW + kk * 16 + cc * 4];
                asm volatile(
                    "mma.sync.aligned.m16n8k16.row.col.f32.bf16.bf16.f32 "
                    "{%0,%1,%2,%3}, {%4,%5,%6,%7}, {%8,%9}, {%0,%1,%2,%3};\n"
                    : "+f"(acc[nt][0]), "+f"(acc[nt][1]), "+f"(acc[nt][2]), "+f"(acc[nt][3])
                    : "r"(qa0.x), "r"(qa1.x), "r"(qa0.y), "r"(qa1.y),
                      "r"(qb.x), "r"(qb.y));
                asm volatile(
                    "mma.sync.aligned.m16n8k16.row.col.f32.bf16.bf16.f32 "
                    "{%0,%1,%2,%3}, {%4,%5,%6,%7}, {%8,%9}, {%0,%1,%2,%3};\n"
                    : "+f"(acc[nt][0]), "+f"(acc[nt][1]), "+f"(acc[nt][2]), "+f"(acc[nt][3])
                    : "r"(qa0.z), "r"(qa1.z), "r"(qa0.w), "r"(qa1.w),
                      "r"(qb.z), "r"(qb.w));
            }
        }

        int row0 = tile * 128 + mb + g;
        float m0 = (row0 < N_NODES) ? 1.f : 0.f;
        float m1 = (row0 + 8 < N_NODES) ? 1.f : 0.f;
        #pragma unroll
        for (int nt = 0; nt < 16; nt++) {
            float bA = sB[nt * 8 + 2 * cc];
            float bB = sB[nt * 8 + 2 * cc + 1];
            float vA = m0 * fmaxf(acc[nt][0] + bA, 0.f) + m1 * fmaxf(acc[nt][2] + bA, 0.f);
            float vB = m0 * fmaxf(acc[nt][1] + bB, 0.f) + m1 * fmaxf(acc[nt][3] + bB, 0.f);
            #pragma unroll
            for (int o = 4; o < 32; o <<= 1) {
                vA += __shfl_xor_sync(0xffffffff, vA, o);
                vB += __shfl_xor_sync(0xffffffff, vB, o);
            }
            if (lane < 4) {
                atomicAdd(&red[nt * 8 + 2 * lane],     vA);
                atomicAdd(&red[nt * 8 + 2 * lane + 1], vB);
            }
        }
    }

    __syncthreads();
    if (tid < 128) atomicAdd(&g_zsum[t][tid], red[tid]);
}

// ---------------- GRU cell: 384 gate-parallel threads ----------------
__global__ void gru_kernel(const float* __restrict__ Wih, const float* __restrict__ Whh,
                           const float* __restrict__ bih, const float* __restrict__ bhh,
                           int t) {
    __shared__ __align__(16) float z[C];
    __shared__ __align__(16) float hs[C];
    __shared__ float gi[3 * C], gh[3 * C];
    int tid = threadIdx.x;      // 384
    if (tid < C) {
        z[tid]  = g_zsum[t][tid] * (1.f / (float)N_NODES);
        hs[tid] = g_h[tid];
    }
    __syncthreads();

    {
        float ai = bih[tid], ah = bhh[tid];
        const float4* Wi4 = (const float4*)(Wih + tid * C);
        const float4* Wh4 = (const float4*)(Whh + tid * C);
        const float4* z4 = (const float4*)z;
        const float4* h4 = (const float4*)hs;
        #pragma unroll 8
        for (int k = 0; k < 32; k++) {
            float4 w = Wi4[k], v = z4[k];
            ai += w.x * v.x + w.y * v.y + w.z * v.z + w.w * v.w;
            float4 u = Wh4[k], hv = h4[k];
            ah += u.x * hv.x + u.y * hv.y + u.z * hv.z + u.w * hv.w;
        }
        gi[tid] = ai; gh[tid] = ah;
    }
    __syncthreads();

    if (tid < C) {
        float r  = 1.f / (1.f + expf(-(gi[tid] + gh[tid])));
        float zg = 1.f / (1.f + expf(-(gi[C + tid] + gh[C + tid])));
        float ng = tanhf(gi[2 * C + tid] + r * gh[2 * C + tid]);
        g_h[tid] = (1.f - zg) * ng + zg * hs[tid];
    }
}

// ---------------- classifier ----------------
__global__ void cls_kernel(const float* __restrict__ Wc, const float* __restrict__ bc,
                           float* __restrict__ out) {
    int tid = threadIdx.x;
    if (tid < OUT_DIM) {
        float acc = bc[tid];
        const float4* W4 = (const float4*)Wc;
        const float4* h4 = (const float4*)g_h;
        #pragma unroll
        for (int k = 0; k < 32; k++) {
            float4 w = W4[tid * 32 + k], h = h4[k];
            acc += w.x * h.x + w.y * h.y + w.z * h.z + w.w * h.w;
        }
        out[tid] = acc;
    }
}

// ---------------- launch: two-stream capture-forked pipeline ----------------
extern "C" void kernel_launch(void* const* d_in, const int* in_sizes, int n_in,
                              void* d_out, int out_size) {
    const float* xs    = (const float*)d_in[0];
    const int*   edges = (const int*)  d_in[1];
    const float* Wg    = (const float*)d_in[2];
    const float* bg    = (const float*)d_in[3];
    const float* Wih   = (const float*)d_in[4];
    const float* Whh   = (const float*)d_in[5];
    const float* bih   = (const float*)d_in[6];
    const float* bhh   = (const float*)d_in[7];
    const float* Wc    = (const float*)d_in[8];
    const float* bc    = (const float*)d_in[9];
    float* out = (float*)d_out;

    cudaFuncSetAttribute(gemm_mean_kernel,
                         cudaFuncAttributeMaxDynamicSharedMemorySize, GEMM_SMEM_BYTES);

    // host-side stream/event objects created fresh each call (kernel_launch is
    // invoked a bounded number of times; intentionally not destroyed so the
    // captured graph's resources stay alive). No device memory involved.
    cudaStream_t sB;
    cudaStreamCreate(&sB);
    cudaEvent_t eInit, eJoin, eB[T_STEPS], eG[T_STEPS];
    cudaEventCreateWithFlags(&eInit, cudaEventDisableTiming);
    cudaEventCreateWithFlags(&eJoin, cudaEventDisableTiming);
    for (int t = 0; t < T_STEPS; t++) {
        cudaEventCreateWithFlags(&eB[t], cudaEventDisableTiming);
        cudaEventCreateWithFlags(&eG[t], cudaEventDisableTiming);
    }

    // main (stream 0): init -> convert -> gathers
    init_kernel<<<(T_STEPS * N_NODES + 255) / 256, 256>>>(Wg);
    cudaEventRecord(eInit, 0);

    // fork: builds on sB (need init's zeroed counters)
    cudaStreamWaitEvent(sB, eInit, 0);
    const int build_bx = (N_EDGES / 4 + 255) / 256;
    for (int t = 0; t < T_STEPS; t++) {
        build_kernel<<<build_bx, 256, 0, sB>>>(edges, t);
        cudaEventRecord(eB[t], sB);
    }

    convert_x_kernel<<<(int)(((size_t)T_STEPS * N_NODES * C / 8 + 255) / 256), 256>>>(xs);

    for (int t = 0; t < T_STEPS; t++) {
        cudaStreamWaitEvent(0, eB[t], 0);     // gather t needs build t
        gather_kernel<<<(N_NODES * 32 + 255) / 256, 256>>>(t);
        cudaEventRecord(eG[t], 0);
    }

    // sB: gemm+gru chain, each gated on its gather
    for (int t = 0; t < T_STEPS; t++) {
        cudaStreamWaitEvent(sB, eG[t], 0);
        gemm_mean_kernel<<<296, 256, GEMM_SMEM_BYTES, sB>>>(bg, t);
        gru_kernel<<<1, 3 * C, 0, sB>>>(Wih, Whh, bih, bhh, t);
    }

    // join and classify
    cudaEventRecord(eJoin, sB);
    cudaStreamWaitEvent(0, eJoin, 0);
    cls_kernel<<<1, 32>>>(Wc, bc, out);
}

// round 8
// speedup vs baseline: 2.9679x; 1.0397x over previous
#include <cuda_runtime.h>
#include <cuda_bf16.h>
#include <math.h>

#define N_NODES 50000
#define N_EDGES 1600000
#define T_STEPS 4
#define C 128
#define OUT_DIM 16
#define CAP 128            // P[deg>=128 | Poisson(32)] ~ 1e-35

#define GATHER_B 6250
#define BUILD_B  1563
#define CONV_B   12500
#define GEMM_B   296
#define N_TILES64 ((N_NODES + 63) / 64)      // 782
#define SROWW 80
#define GEMM_DSM (128 * SROWW * 4 + 2 * 128 * 4)   // 41984

// ---------------- scratch (device globals; no allocs allowed) ----------------
__device__ int   g_cnt[T_STEPS][N_NODES];
__device__ int   g_bkt[T_STEPS][N_NODES][CAP];                 // 102.4 MB
__device__ __align__(16) __nv_bfloat16 g_x_bf[(size_t)T_STEPS * N_NODES * C];
__device__ __align__(16) __nv_bfloat16 g_aggx_bf[T_STEPS][(N_NODES + 64) * C]; // padded, PERMUTED
__device__ __align__(16) __nv_bfloat16 g_Wbf[C * C];           // PERMUTED word order
__device__ __align__(16) float g_zsum[T_STEPS][C];
__device__ __align__(16) float g_h[C];

// word permutation within a 64-word K-row: the 4 mma fragment words of a
// ks-pair are 16B-contiguous.
__device__ __forceinline__ int permw(int w) {
    int ks = w >> 3, cc = w & 3, half = (w >> 2) & 1;
    return (ks >> 1) * 16 + cc * 4 + (ks & 1) * 2 + half;
}

// ---------------- init ----------------
__global__ void init_kernel(const float* __restrict__ W) {
    int i = blockIdx.x * blockDim.x + threadIdx.x;
    if (i < T_STEPS * N_NODES) ((int*)g_cnt)[i] = 0;
    if (i < C * C) {
        int j = i >> 7, k = i & 127;
        g_Wbf[j * 128 + permw(k >> 1) * 2 + (k & 1)] = __float2bfloat16(W[i]);
    }
    if (i < T_STEPS * C) ((float*)g_zsum)[i] = 0.f;
    if (i < C) g_h[i] = 0.f;
    if (i < T_STEPS * 64 * C / 2) {        // zero aggx pad rows (avoid NaN in masked mma rows)
        int t = i >> 12, w = i & 4095;
        ((unsigned int*)g_aggx_bf[t])[N_NODES * 64 + w] = 0u;
    }
}

// ---------------- helpers ----------------
__device__ __forceinline__ float4 bf8_to_f4(uint2 v) {
    float2 f0 = __bfloat1622float2(*(__nv_bfloat162*)&v.x);
    float2 f1 = __bfloat1622float2(*(__nv_bfloat162*)&v.y);
    return make_float4(f0.x, f0.y, f1.x, f1.y);
}
__device__ __forceinline__ unsigned int hadd2b(unsigned int a, unsigned int b) {
    __nv_bfloat162 r = __hadd2(*(__nv_bfloat162*)&a, *(__nv_bfloat162*)&b);
    return *(unsigned int*)&r;
}

// ================= mega kernel: gather / build / convert roles =================
__global__ __launch_bounds__(256, 6) void mega_kernel(
    const float* __restrict__ xs, const int* __restrict__ edges,
    int convFlag, int buildT, int gatherT)
{
    int b = blockIdx.x;
    int tid = threadIdx.x;

    // ---- gather role ----
    int nG = (gatherT >= 0) ? GATHER_B : 0;
    if (b < nG) {
        int t = gatherT;
        int node = (b * 256 + tid) >> 5;
        int lane = tid & 31;
        if (node >= N_NODES) return;
        const uint2* __restrict__ xb = ((const uint2*)g_x_bf) + (size_t)t * N_NODES * 32;
        const int* __restrict__ bkt = g_bkt[t][node];
        float4 acc = bf8_to_f4(xb[node * 32 + lane]);   // self loop
        int deg = min(g_cnt[t][node], CAP);
        int i = 0;
        for (; i + 3 < deg; i += 4) {
            int s0 = bkt[i], s1 = bkt[i + 1], s2 = bkt[i + 2], s3 = bkt[i + 3];
            uint2 a = xb[s0 * 32 + lane];
            uint2 bb = xb[s1 * 32 + lane];
            uint2 c = xb[s2 * 32 + lane];
            uint2 d = xb[s3 * 32 + lane];
            unsigned int sx = hadd2b(hadd2b(a.x, bb.x), hadd2b(c.x, d.x));
            unsigned int sy = hadd2b(hadd2b(a.y, bb.y), hadd2b(c.y, d.y));
            float2 f0 = __bfloat1622float2(*(__nv_bfloat162*)&sx);
            float2 f1 = __bfloat1622float2(*(__nv_bfloat162*)&sy);
            acc.x += f0.x; acc.y += f0.y; acc.z += f1.x; acc.w += f1.y;
        }
        for (; i < deg; i++) {
            float4 a = bf8_to_f4(xb[bkt[i] * 32 + lane]);
            acc.x += a.x; acc.y += a.y; acc.z += a.z; acc.w += a.w;
        }
        float inv = 1.f / (float)(deg + 1);
        __nv_bfloat162 p0 = __floats2bfloat162_rn(acc.x * inv, acc.y * inv);
        __nv_bfloat162 p1 = __floats2bfloat162_rn(acc.z * inv, acc.w * inv);
        unsigned int* row = ((unsigned int*)g_aggx_bf[t]) + node * 64;
        row[permw(2 * lane)]     = *(unsigned int*)&p0;
        row[permw(2 * lane + 1)] = *(unsigned int*)&p1;
        return;
    }
    b -= nG;

    // ---- build role ----
    int nB = (buildT >= 0) ? BUILD_B : 0;
    if (b < nB) {
        int t = buildT;
        int e4 = b * 256 + tid;
        const int* base = edges + (size_t)t * 2 * N_EDGES;
        const int4* src4 = (const int4*)base;
        const int4* dst4 = (const int4*)(base + N_EDGES);
        if (e4 < N_EDGES / 4) {
            int4 s = src4[e4];
            int4 d = dst4[e4];
            int p;
            p = atomicAdd(&g_cnt[t][d.x], 1); if (p < CAP) g_bkt[t][d.x][p] = s.x;
            p = atomicAdd(&g_cnt[t][d.y], 1); if (p < CAP) g_bkt[t][d.y][p] = s.y;
            p = atomicAdd(&g_cnt[t][d.z], 1); if (p < CAP) g_bkt[t][d.z][p] = s.z;
            p = atomicAdd(&g_cnt[t][d.w], 1); if (p < CAP) g_bkt[t][d.w][p] = s.w;
        }
        return;
    }
    b -= nB;

    // ---- convert role (all timesteps) ----
    if (convFlag) {
        size_t i = (size_t)b * 256 + tid;
        const size_t total8 = (size_t)T_STEPS * N_NODES * C / 8;
        if (i >= total8) return;
        const float4* x4 = (const float4*)xs;
        float4 a = x4[2 * i], bb = x4[2 * i + 1];
        __nv_bfloat162 p0 = __floats2bfloat162_rn(a.x, a.y);
        __nv_bfloat162 p1 = __floats2bfloat162_rn(a.z, a.w);
        __nv_bfloat162 p2 = __floats2bfloat162_rn(bb.x, bb.y);
        __nv_bfloat162 p3 = __floats2bfloat162_rn(bb.z, bb.w);
        uint4 o;
        o.x = *(unsigned int*)&p0; o.y = *(unsigned int*)&p1;
        o.z = *(unsigned int*)&p2; o.w = *(unsigned int*)&p3;
        ((uint4*)g_x_bf)[i] = o;
    }
}

// ================= gemm (+gru) kernel =================
// u = aggx @ W^T + b; zsum[t] += sum_n relu(u_n). TILE_M=64, A direct from
// global (permuted fragment layout), W staged in SMEM (SROWW=80, conflict-free).
__global__ __launch_bounds__(256, 4) void gemm_gru_kernel(
    const float* __restrict__ bias,
    const float* __restrict__ Wih, const float* __restrict__ Whh,
    const float* __restrict__ bih, const float* __restrict__ bhh,
    int gemmT, int gruT)
{
    int nM = (gemmT >= 0) ? GEMM_B : 0;
    int blk = blockIdx.x;
    int tid = threadIdx.x;

    if (blk < nM) {
        extern __shared__ __align__(16) char dsm[];
        unsigned int* sWw = (unsigned int*)dsm;            // 128 x 80 words
        float* sB  = (float*)(sWw + 128 * SROWW);          // 128
        float* red = sB + 128;                             // 128

        const int lane = tid & 31;
        const int warp = tid >> 5;
        const int g = lane >> 2;
        const int cc = lane & 3;

        {   // stage permuted W
            const int4* Wg = (const int4*)g_Wbf;
            #pragma unroll
            for (int i = 0; i < 8; i++) {
                int idx = tid + i * 256;
                int row = idx >> 4, cv = idx & 15;
                *(int4*)&sWw[row * SROWW + cv * 4] = Wg[idx];
            }
        }
        if (tid < 128) { sB[tid] = bias[tid]; red[tid] = 0.f; }
        __syncthreads();

        const unsigned int* __restrict__ Ag = (const unsigned int*)g_aggx_bf[gemmT];
        const int mg = (warp & 3) * 16;     // row group within 64-row tile
        const int ch = warp >> 2;           // column half (0/1)

        for (int tile = blk; tile < N_TILES64; tile += GEMM_B) {
            int r0 = tile * 64 + mg + g;
            int r1 = r0 + 8;

            float acc[8][4];
            #pragma unroll
            for (int nt = 0; nt < 8; nt++) {
                acc[nt][0] = 0.f; acc[nt][1] = 0.f; acc[nt][2] = 0.f; acc[nt][3] = 0.f;
            }

            #pragma unroll
            for (int kk = 0; kk < 4; kk++) {
                uint4 qa0 = *(const uint4*)&Ag[r0 * 64 + kk * 16 + cc * 4];
                uint4 qa1 = *(const uint4*)&Ag[r1 * 64 + kk * 16 + cc * 4];
                #pragma unroll
                for (int nt = 0; nt < 8; nt++) {
                    int ncol = ch * 8 + nt;
                    uint4 qb = *(const uint4*)&sWw[(ncol * 8 + g) * SROWW + kk * 16 + cc * 4];
                    asm volatile(
                        "mma.sync.aligned.m16n8k16.row.col.f32.bf16.bf16.f32 "
                        "{%0,%1,%2,%3}, {%4,%5,%6,%7}, {%8,%9}, {%0,%1,%2,%3};\n"
                        : "+f"(acc[nt][0]), "+f"(acc[nt][1]), "+f"(acc[nt][2]), "+f"(acc[nt][3])
                        : "r"(qa0.x), "r"(qa1.x), "r"(qa0.y), "r"(qa1.y),
                          "r"(qb.x), "r"(qb.y));
                    asm volatile(
                        "mma.sync.aligned.m16n8k16.row.col.f32.bf16.bf16.f32 "
                        "{%0,%1,%2,%3}, {%4,%5,%6,%7}, {%8,%9}, {%0,%1,%2,%3};\n"
                        : "+f"(acc[nt][0]), "+f"(acc[nt][1]), "+f"(acc[nt][2]), "+f"(acc[nt][3])
                        : "r"(qa0.z), "r"(qa1.z), "r"(qa0.w), "r"(qa1.w),
                          "r"(qb.z), "r"(qb.w));
                }
            }

            float m0 = (r0 < N_NODES) ? 1.f : 0.f;
            float m1 = (r1 < N_NODES) ? 1.f : 0.f;
            #pragma unroll
            for (int nt = 0; nt < 8; nt++) {
                int ncol = ch * 8 + nt;
                float bA = sB[ncol * 8 + 2 * cc];
                float bB = sB[ncol * 8 + 2 * cc + 1];
                float vA = m0 * fmaxf(acc[nt][0] + bA, 0.f) + m1 * fmaxf(acc[nt][2] + bA, 0.f);
                float vB = m0 * fmaxf(acc[nt][1] + bB, 0.f) + m1 * fmaxf(acc[nt][3] + bB, 0.f);
                #pragma unroll
                for (int o = 4; o < 32; o <<= 1) {
                    vA += __shfl_xor_sync(0xffffffff, vA, o);
                    vB += __shfl_xor_sync(0xffffffff, vB, o);
                }
                if (lane < 4) {
                    atomicAdd(&red[ncol * 8 + 2 * lane],     vA);
                    atomicAdd(&red[ncol * 8 + 2 * lane + 1], vB);
                }
            }
        }

        __syncthreads();
        if (tid < 128) atomicAdd(&g_zsum[gemmT][tid], red[tid]);
        return;
    }

    // ---- gru role (one block, 256 threads covering 384 gate rows) ----
    if (gruT >= 0 && blk == nM) {
        __shared__ __align__(16) float z[C];
        __shared__ __align__(16) float hs[C];
        __shared__ float gi[3 * C], gh[3 * C];
        if (tid < C) {
            z[tid]  = g_zsum[gruT][tid] * (1.f / (float)N_NODES);
            hs[tid] = g_h[tid];
        }
        __syncthreads();

        #pragma unroll
        for (int rep = 0; rep < 2; rep++) {
            int r = tid + rep * 256;
            if (r < 3 * C) {
                float ai = bih[r], ah = bhh[r];
                const float4* Wi4 = (const float4*)(Wih + r * C);
                const float4* Wh4 = (const float4*)(Whh + r * C);
                const float4* z4 = (const float4*)z;
                const float4* h4 = (const float4*)hs;
                #pragma unroll 8
                for (int k = 0; k < 32; k++) {
                    float4 w = Wi4[k], v = z4[k];
                    ai += w.x * v.x + w.y * v.y + w.z * v.z + w.w * v.w;
                    float4 u = Wh4[k], hv = h4[k];
                    ah += u.x * hv.x + u.y * hv.y + u.z * hv.z + u.w * hv.w;
                }
                gi[r] = ai; gh[r] = ah;
            }
        }
        __syncthreads();

        if (tid < C) {
            float r  = 1.f / (1.f + expf(-(gi[tid] + gh[tid])));
            float zg = 1.f / (1.f + expf(-(gi[C + tid] + gh[C + tid])));
            float ng = tanhf(gi[2 * C + tid] + r * gh[2 * C + tid]);
            g_h[tid] = (1.f - zg) * ng + zg * hs[tid];
        }
    }
}

// ---------------- classifier ----------------
__global__ void cls_kernel(const float* __restrict__ Wc, const float* __restrict__ bc,
                           float* __restrict__ out) {
    int tid = threadIdx.x;
    if (tid < OUT_DIM) {
        float acc = bc[tid];
        const float4* W4 = (const float4*)Wc;
        const float4* h4 = (const float4*)g_h;
        #pragma unroll
        for (int k = 0; k < 32; k++) {
            float4 w = W4[tid * 32 + k], h = h4[k];
            acc += w.x * h.x + w.y * h.y + w.z * h.z + w.w * h.w;
        }
        out[tid] = acc;
    }
}

// ---------------- launch: single stream, role-pipelined ----------------
extern "C" void kernel_launch(void* const* d_in, const int* in_sizes, int n_in,
                              void* d_out, int out_size) {
    const float* xs    = (const float*)d_in[0];
    const int*   edges = (const int*)  d_in[1];
    const float* Wg    = (const float*)d_in[2];
    const float* bg    = (const float*)d_in[3];
    const float* Wih   = (const float*)d_in[4];
    const float* Whh   = (const float*)d_in[5];
    const float* bih   = (const float*)d_in[6];
    const float* bhh   = (const float*)d_in[7];
    const float* Wc    = (const float*)d_in[8];
    const float* bc    = (const float*)d_in[9];
    float* out = (float*)d_out;

    // init: counters, permuted W, zsum, h, aggx pad rows
    init_kernel<<<(T_STEPS * N_NODES + 255) / 256, 256>>>(Wg);

    // L2: convert(all) + build(0)
    mega_kernel<<<CONV_B + BUILD_B, 256>>>(xs, edges, 1, 0, -1);
    // L3: gather(0) + build(1)
    mega_kernel<<<GATHER_B + BUILD_B, 256>>>(xs, edges, 0, 1, 0);
    // L4: gemm(0)
    gemm_gru_kernel<<<GEMM_B, 256, GEMM_DSM>>>(bg, Wih, Whh, bih, bhh, 0, -1);
    // L5: gather(1) + build(2)
    mega_kernel<<<GATHER_B + BUILD_B, 256>>>(xs, edges, 0, 2, 1);
    // L6: gemm(1) + gru(0)
    gemm_gru_kernel<<<GEMM_B + 1, 256, GEMM_DSM>>>(bg, Wih, Whh, bih, bhh, 1, 0);
    // L7: gather(2) + build(3)
    mega_kernel<<<GATHER_B + BUILD_B, 256>>>(xs, edges, 0, 3, 2);
    // L8: gemm(2) + gru(1)
    gemm_gru_kernel<<<GEMM_B + 1, 256, GEMM_DSM>>>(bg, Wih, Whh, bih, bhh, 2, 1);
    // L9: gather(3)
    mega_kernel<<<GATHER_B, 256>>>(xs, edges, 0, -1, 3);
    // L10: gemm(3) + gru(2)
    gemm_gru_kernel<<<GEMM_B + 1, 256, GEMM_DSM>>>(bg, Wih, Whh, bih, bhh, 3, 2);
    // L11: gru(3)
    gemm_gru_kernel<<<1, 256, 0>>>(bg, Wih, Whh, bih, bhh, -1, 3);
    // L12: classifier
    cls_kernel<<<1, 32>>>(Wc, bc, out);
}

// round 9
// speedup vs baseline: 3.0569x; 1.0300x over previous
#include <cuda_runtime.h>
#include <cuda_bf16.h>
#include <math.h>

#define N_NODES 50000
#define N_EDGES 1600000
#define T_STEPS 4
#define C 128
#define OUT_DIM 16
#define CAP 128            // P[deg>=128 | Poisson(32)] ~ 1e-35

#define GATHER_B 6250
#define BUILD_B  1563
#define CONV1_B  3125      // one timestep: N*C/8/256
#define GEMM_B   592       // 4 CTAs/SM over 148 SMs
#define N_TILES64 ((N_NODES + 63) / 64)      // 782
#define SROWW 80
#define GEMM_DSM (128 * SROWW * 4 + 2 * 128 * 4)   // 41984

// ---------------- scratch (device globals; no allocs allowed) ----------------
__device__ int   g_cnt[T_STEPS][N_NODES];
__device__ int   g_bkt[T_STEPS][N_NODES][CAP];                 // 102.4 MB
__device__ __align__(16) __nv_bfloat16 g_x_bf[(size_t)T_STEPS * N_NODES * C];
__device__ __align__(16) __nv_bfloat16 g_aggx_bf[T_STEPS][(N_NODES + 64) * C]; // padded, PERMUTED
__device__ __align__(16) __nv_bfloat16 g_Wbf[C * C];           // PERMUTED word order
__device__ __align__(16) float g_zsum[T_STEPS][C];
__device__ __align__(16) float g_h[C];

// word permutation within a 64-word K-row: the 4 mma fragment words of a
// ks-pair are 16B-contiguous.
__device__ __forceinline__ int permw(int w) {
    int ks = w >> 3, cc = w & 3, half = (w >> 2) & 1;
    return (ks >> 1) * 16 + cc * 4 + (ks & 1) * 2 + half;
}

// ---------------- init ----------------
__global__ void init_kernel(const float* __restrict__ W) {
    int i = blockIdx.x * blockDim.x + threadIdx.x;
    if (i < T_STEPS * N_NODES) ((int*)g_cnt)[i] = 0;
    if (i < C * C) {
        int j = i >> 7, k = i & 127;
        g_Wbf[j * 128 + permw(k >> 1) * 2 + (k & 1)] = __float2bfloat16(W[i]);
    }
    if (i < T_STEPS * C) ((float*)g_zsum)[i] = 0.f;
    if (i < C) g_h[i] = 0.f;
    if (i < T_STEPS * 64 * C / 2) {        // zero aggx pad rows
        int t = i >> 12, w = i & 4095;
        ((unsigned int*)g_aggx_bf[t])[N_NODES * 64 + w] = 0u;
    }
}

// ---------------- helpers ----------------
__device__ __forceinline__ float4 bf8_to_f4(uint2 v) {
    float2 f0 = __bfloat1622float2(*(__nv_bfloat162*)&v.x);
    float2 f1 = __bfloat1622float2(*(__nv_bfloat162*)&v.y);
    return make_float4(f0.x, f0.y, f1.x, f1.y);
}
__device__ __forceinline__ unsigned int hadd2b(unsigned int a, unsigned int b) {
    __nv_bfloat162 r = __hadd2(*(__nv_bfloat162*)&a, *(__nv_bfloat162*)&b);
    return *(unsigned int*)&r;
}

// ================= mega kernel: gather / build / convert(one t) roles =================
__global__ __launch_bounds__(256, 6) void mega_kernel(
    const float* __restrict__ xs, const int* __restrict__ edges,
    int convT, int buildT, int gatherT)
{
    int b = blockIdx.x;
    int tid = threadIdx.x;

    // ---- gather role ----
    int nG = (gatherT >= 0) ? GATHER_B : 0;
    if (b < nG) {
        int t = gatherT;
        int node = (b * 256 + tid) >> 5;
        int lane = tid & 31;
        if (node >= N_NODES) return;
        const uint2* __restrict__ xb = ((const uint2*)g_x_bf) + (size_t)t * N_NODES * 32;
        const int* __restrict__ bkt = g_bkt[t][node];
        float4 acc = bf8_to_f4(xb[node * 32 + lane]);   // self loop
        int deg = min(g_cnt[t][node], CAP);
        int i = 0;
        for (; i + 3 < deg; i += 4) {
            int s0 = bkt[i], s1 = bkt[i + 1], s2 = bkt[i + 2], s3 = bkt[i + 3];
            uint2 a = xb[s0 * 32 + lane];
            uint2 bb = xb[s1 * 32 + lane];
            uint2 c = xb[s2 * 32 + lane];
            uint2 d = xb[s3 * 32 + lane];
            unsigned int sx = hadd2b(hadd2b(a.x, bb.x), hadd2b(c.x, d.x));
            unsigned int sy = hadd2b(hadd2b(a.y, bb.y), hadd2b(c.y, d.y));
            float2 f0 = __bfloat1622float2(*(__nv_bfloat162*)&sx);
            float2 f1 = __bfloat1622float2(*(__nv_bfloat162*)&sy);
            acc.x += f0.x; acc.y += f0.y; acc.z += f1.x; acc.w += f1.y;
        }
        for (; i < deg; i++) {
            float4 a = bf8_to_f4(xb[bkt[i] * 32 + lane]);
            acc.x += a.x; acc.y += a.y; acc.z += a.z; acc.w += a.w;
        }
        float inv = 1.f / (float)(deg + 1);
        __nv_bfloat162 p0 = __floats2bfloat162_rn(acc.x * inv, acc.y * inv);
        __nv_bfloat162 p1 = __floats2bfloat162_rn(acc.z * inv, acc.w * inv);
        unsigned int* row = ((unsigned int*)g_aggx_bf[t]) + node * 64;
        row[permw(2 * lane)]     = *(unsigned int*)&p0;
        row[permw(2 * lane + 1)] = *(unsigned int*)&p1;
        return;
    }
    b -= nG;

    // ---- build role ----
    int nB = (buildT >= 0) ? BUILD_B : 0;
    if (b < nB) {
        int t = buildT;
        int e4 = b * 256 + tid;
        const int* base = edges + (size_t)t * 2 * N_EDGES;
        const int4* src4 = (const int4*)base;
        const int4* dst4 = (const int4*)(base + N_EDGES);
        if (e4 < N_EDGES / 4) {
            int4 s = src4[e4];
            int4 d = dst4[e4];
            int p;
            p = atomicAdd(&g_cnt[t][d.x], 1); if (p < CAP) g_bkt[t][d.x][p] = s.x;
            p = atomicAdd(&g_cnt[t][d.y], 1); if (p < CAP) g_bkt[t][d.y][p] = s.y;
            p = atomicAdd(&g_cnt[t][d.z], 1); if (p < CAP) g_bkt[t][d.z][p] = s.z;
            p = atomicAdd(&g_cnt[t][d.w], 1); if (p < CAP) g_bkt[t][d.w][p] = s.w;
        }
        return;
    }
    b -= nB;

    // ---- convert role (one timestep) ----
    if (convT >= 0) {
        size_t i = (size_t)b * 256 + tid;
        const size_t total8 = (size_t)N_NODES * C / 8;
        if (i >= total8) return;
        const float4* x4 = ((const float4*)xs) + (size_t)convT * N_NODES * C / 4;
        float4 a = x4[2 * i], bb = x4[2 * i + 1];
        __nv_bfloat162 p0 = __floats2bfloat162_rn(a.x, a.y);
        __nv_bfloat162 p1 = __floats2bfloat162_rn(a.z, a.w);
        __nv_bfloat162 p2 = __floats2bfloat162_rn(bb.x, bb.y);
        __nv_bfloat162 p3 = __floats2bfloat162_rn(bb.z, bb.w);
        uint4 o;
        o.x = *(unsigned int*)&p0; o.y = *(unsigned int*)&p1;
        o.z = *(unsigned int*)&p2; o.w = *(unsigned int*)&p3;
        ((uint4*)g_x_bf)[(size_t)convT * N_NODES * C / 8 + i] = o;
    }
}

// ================= gemm (+gru, +cls) kernel =================
__global__ __launch_bounds__(256, 4) void gemm_gru_kernel(
    const float* __restrict__ bias,
    const float* __restrict__ Wih, const float* __restrict__ Whh,
    const float* __restrict__ bih, const float* __restrict__ bhh,
    const float* __restrict__ Wc, const float* __restrict__ bc,
    float* __restrict__ out,
    int gemmT, int gruT, int doCls)
{
    int nM = (gemmT >= 0) ? GEMM_B : 0;
    int blk = blockIdx.x;
    int tid = threadIdx.x;

    if (blk < nM) {
        extern __shared__ __align__(16) char dsm[];
        unsigned int* sWw = (unsigned int*)dsm;            // 128 x 80 words
        float* sB  = (float*)(sWw + 128 * SROWW);          // 128
        float* red = sB + 128;                             // 128

        const int lane = tid & 31;
        const int warp = tid >> 5;
        const int g = lane >> 2;
        const int cc = lane & 3;

        {   // stage permuted W
            const int4* Wg = (const int4*)g_Wbf;
            #pragma unroll
            for (int i = 0; i < 8; i++) {
                int idx = tid + i * 256;
                int row = idx >> 4, cv = idx & 15;
                *(int4*)&sWw[row * SROWW + cv * 4] = Wg[idx];
            }
        }
        if (tid < 128) { sB[tid] = bias[tid]; red[tid] = 0.f; }
        __syncthreads();

        const unsigned int* __restrict__ Ag = (const unsigned int*)g_aggx_bf[gemmT];
        const int mg = (warp & 3) * 16;     // row group within 64-row tile
        const int ch = warp >> 2;           // column half (0/1)

        for (int tile = blk; tile < N_TILES64; tile += GEMM_B) {
            int r0 = tile * 64 + mg + g;
            int r1 = r0 + 8;

            float acc[8][4];
            #pragma unroll
            for (int nt = 0; nt < 8; nt++) {
                acc[nt][0] = 0.f; acc[nt][1] = 0.f; acc[nt][2] = 0.f; acc[nt][3] = 0.f;
            }

            #pragma unroll
            for (int kk = 0; kk < 4; kk++) {
                uint4 qa0 = *(const uint4*)&Ag[r0 * 64 + kk * 16 + cc * 4];
                uint4 qa1 = *(const uint4*)&Ag[r1 * 64 + kk * 16 + cc * 4];
                #pragma unroll
                for (int nt = 0; nt < 8; nt++) {
                    int ncol = ch * 8 + nt;
                    uint4 qb = *(const uint4*)&sWw[(ncol * 8 + g) * SROWW + kk * 16 + cc * 4];
                    asm volatile(
                        "mma.sync.aligned.m16n8k16.row.col.f32.bf16.bf16.f32 "
                        "{%0,%1,%2,%3}, {%4,%5,%6,%7}, {%8,%9}, {%0,%1,%2,%3};\n"
                        : "+f"(acc[nt][0]), "+f"(acc[nt][1]), "+f"(acc[nt][2]), "+f"(acc[nt][3])
                        : "r"(qa0.x), "r"(qa1.x), "r"(qa0.y), "r"(qa1.y),
                          "r"(qb.x), "r"(qb.y));
                    asm volatile(
                        "mma.sync.aligned.m16n8k16.row.col.f32.bf16.bf16.f32 "
                        "{%0,%1,%2,%3}, {%4,%5,%6,%7}, {%8,%9}, {%0,%1,%2,%3};\n"
                        : "+f"(acc[nt][0]), "+f"(acc[nt][1]), "+f"(acc[nt][2]), "+f"(acc[nt][3])
                        : "r"(qa0.z), "r"(qa1.z), "r"(qa0.w), "r"(qa1.w),
                          "r"(qb.z), "r"(qb.w));
                }
            }

            float m0 = (r0 < N_NODES) ? 1.f : 0.f;
            float m1 = (r1 < N_NODES) ? 1.f : 0.f;
            #pragma unroll
            for (int nt = 0; nt < 8; nt++) {
                int ncol = ch * 8 + nt;
                float bA = sB[ncol * 8 + 2 * cc];
                float bB = sB[ncol * 8 + 2 * cc + 1];
                float vA = m0 * fmaxf(acc[nt][0] + bA, 0.f) + m1 * fmaxf(acc[nt][2] + bA, 0.f);
                float vB = m0 * fmaxf(acc[nt][1] + bB, 0.f) + m1 * fmaxf(acc[nt][3] + bB, 0.f);
                #pragma unroll
                for (int o = 4; o < 32; o <<= 1) {
                    vA += __shfl_xor_sync(0xffffffff, vA, o);
                    vB += __shfl_xor_sync(0xffffffff, vB, o);
                }
                if (lane < 4) {
                    atomicAdd(&red[ncol * 8 + 2 * lane],     vA);
                    atomicAdd(&red[ncol * 8 + 2 * lane + 1], vB);
                }
            }
        }

        __syncthreads();
        if (tid < 128) atomicAdd(&g_zsum[gemmT][tid], red[tid]);
        return;
    }

    // ---- gru role (one block) + optional fused classifier ----
    if (gruT >= 0 && blk == nM) {
        __shared__ __align__(16) float z[C];
        __shared__ __align__(16) float hs[C];
        __shared__ float gi[3 * C], gh[3 * C];
        if (tid < C) {
            z[tid]  = g_zsum[gruT][tid] * (1.f / (float)N_NODES);
            hs[tid] = g_h[tid];
        }
        __syncthreads();

        #pragma unroll
        for (int rep = 0; rep < 2; rep++) {
            int r = tid + rep * 256;
            if (r < 3 * C) {
                float ai = bih[r], ah = bhh[r];
                const float4* Wi4 = (const float4*)(Wih + r * C);
                const float4* Wh4 = (const float4*)(Whh + r * C);
                const float4* z4 = (const float4*)z;
                const float4* h4 = (const float4*)hs;
                #pragma unroll 8
                for (int k = 0; k < 32; k++) {
                    float4 w = Wi4[k], v = z4[k];
                    ai += w.x * v.x + w.y * v.y + w.z * v.z + w.w * v.w;
                    float4 u = Wh4[k], hv = h4[k];
                    ah += u.x * hv.x + u.y * hv.y + u.z * hv.z + u.w * hv.w;
                }
                gi[r] = ai; gh[r] = ah;
            }
        }
        __syncthreads();

        if (tid < C) {
            float r  = 1.f / (1.f + expf(-(gi[tid] + gh[tid])));
            float zg = 1.f / (1.f + expf(-(gi[C + tid] + gh[C + tid])));
            float ng = tanhf(gi[2 * C + tid] + r * gh[2 * C + tid]);
            float hn = (1.f - zg) * ng + zg * hs[tid];
            g_h[tid] = hn;
            hs[tid] = hn;          // reuse for fused cls
        }
        if (doCls) {
            __syncthreads();
            if (tid < OUT_DIM) {
                float acc = bc[tid];
                const float4* W4 = (const float4*)Wc;
                const float4* h4 = (const float4*)hs;
                #pragma unroll
                for (int k = 0; k < 32; k++) {
                    float4 w = W4[tid * 32 + k], h = h4[k];
                    acc += w.x * h.x + w.y * h.y + w.z * h.z + w.w * h.w;
                }
                out[tid] = acc;
            }
        }
    }
}

// ---------------- launch: single stream, role-pipelined ----------------
extern "C" void kernel_launch(void* const* d_in, const int* in_sizes, int n_in,
                              void* d_out, int out_size) {
    const float* xs    = (const float*)d_in[0];
    const int*   edges = (const int*)  d_in[1];
    const float* Wg    = (const float*)d_in[2];
    const float* bg    = (const float*)d_in[3];
    const float* Wih   = (const float*)d_in[4];
    const float* Whh   = (const float*)d_in[5];
    const float* bih   = (const float*)d_in[6];
    const float* bhh   = (const float*)d_in[7];
    const float* Wc    = (const float*)d_in[8];
    const float* bc    = (const float*)d_in[9];
    float* out = (float*)d_out;

    init_kernel<<<(T_STEPS * N_NODES + 255) / 256, 256>>>(Wg);

    // L2: conv(0) + build(0)
    mega_kernel<<<CONV1_B + BUILD_B, 256>>>(xs, edges, 0, 0, -1);
    // L3: gather(0) + build(1) + conv(1)
    mega_kernel<<<GATHER_B + BUILD_B + CONV1_B, 256>>>(xs, edges, 1, 1, 0);
    // L4: gemm(0)
    gemm_gru_kernel<<<GEMM_B, 256, GEMM_DSM>>>(bg, Wih, Whh, bih, bhh, Wc, bc, out, 0, -1, 0);
    // L5: gather(1) + build(2) + conv(2)
    mega_kernel<<<GATHER_B + BUILD_B + CONV1_B, 256>>>(xs, edges, 2, 2, 1);
    // L6: gemm(1) + gru(0)
    gemm_gru_kernel<<<GEMM_B + 1, 256, GEMM_DSM>>>(bg, Wih, Whh, bih, bhh, Wc, bc, out, 1, 0, 0);
    // L7: gather(2) + build(3) + conv(3)
    mega_kernel<<<GATHER_B + BUILD_B + CONV1_B, 256>>>(xs, edges, 3, 3, 2);
    // L8: gemm(2) + gru(1)
    gemm_gru_kernel<<<GEMM_B + 1, 256, GEMM_DSM>>>(bg, Wih, Whh, bih, bhh, Wc, bc, out, 2, 1, 0);
    // L9: gather(3)
    mega_kernel<<<GATHER_B, 256>>>(xs, edges, -1, -1, 3);
    // L10: gemm(3) + gru(2)
    gemm_gru_kernel<<<GEMM_B + 1, 256, GEMM_DSM>>>(bg, Wih, Whh, bih, bhh, Wc, bc, out, 3, 2, 0);
    // L11: gru(3) + fused classifier
    gemm_gru_kernel<<<1, 256, 0>>>(bg, Wih, Whh, bih, bhh, Wc, bc, out, -1, 3, 1);
}